// round 8
// baseline (speedup 1.0000x reference)
#include <cuda_runtime.h>
#include <cuda_bf16.h>
#include <math.h>
#include <stdint.h>

#define TT   1000
#define NB   32
#define NPAIR 16
#define VV   2000
#define CC   512
#define UU   100
#define SS   201
#define EXT  104
#define NEGF (-1.0e30f)
#define LOG2E 1.4426950408889634f
#define LN2   0.6931471805599453

#define BMg 128
#define BNg 128
#define BKg 32
#define NSTG (CC / BKg)
#define ROWB 80
#define PLANE_B (BMg * ROWB)
#define STAGE_B (4 * PLANE_B)
#define GEMM_SMEM (2 * STAGE_B)

__device__ float g_logits[(size_t)NB * TT * VV];
__device__ float g_lp[(size_t)NB * TT * EXT];   // log2-probs at ext classes
__device__ float g_kl[NPAIR * TT];
__device__ float g_ctc[NB];
__device__ __nv_bfloat16 g_Ahi[(size_t)NB * TT * CC];
__device__ __nv_bfloat16 g_Alo[(size_t)NB * TT * CC];
__device__ __nv_bfloat16 g_Whi[(size_t)2048 * CC];
__device__ __nv_bfloat16 g_Wlo[(size_t)2048 * CC];

__device__ __forceinline__ uint32_t s2u(const void* p) {
    uint32_t a;
    asm("{ .reg .u64 t; cvta.to.shared.u64 t, %1; cvt.u32.u64 %0, t; }" : "=r"(a) : "l"(p));
    return a;
}
__device__ __forceinline__ void cp_async16(uint32_t dst, const void* src) {
    asm volatile("cp.async.cg.shared.global [%0], [%1], 16;" :: "r"(dst), "l"(src) : "memory");
}
__device__ __forceinline__ void cp_commit() {
    asm volatile("cp.async.commit_group;" ::: "memory");
}
template <int N>
__device__ __forceinline__ void cp_wait() {
    asm volatile("cp.async.wait_group %0;" :: "n"(N) : "memory");
}
__device__ __forceinline__ void ldsm4(uint32_t& r0, uint32_t& r1, uint32_t& r2, uint32_t& r3,
                                      uint32_t a) {
    asm volatile("ldmatrix.sync.aligned.m8n8.x4.shared.b16 {%0,%1,%2,%3}, [%4];"
                 : "=r"(r0), "=r"(r1), "=r"(r2), "=r"(r3) : "r"(a));
}
__device__ __forceinline__ void mma16816(float* c, const uint32_t* a, const uint32_t* b) {
    asm volatile(
        "mma.sync.aligned.m16n8k16.row.col.f32.bf16.bf16.f32 "
        "{%0,%1,%2,%3}, {%4,%5,%6,%7}, {%8,%9}, {%0,%1,%2,%3};"
        : "+f"(c[0]), "+f"(c[1]), "+f"(c[2]), "+f"(c[3])
        : "r"(a[0]), "r"(a[1]), "r"(a[2]), "r"(a[3]), "r"(b[0]), "r"(b[1]));
}

__device__ __forceinline__ float bsum(float v, float* sh) {
    #pragma unroll
    for (int o = 16; o; o >>= 1) v += __shfl_xor_sync(0xffffffffu, v, o);
    __syncthreads();
    if ((threadIdx.x & 31) == 0) sh[threadIdx.x >> 5] = v;
    __syncthreads();
    if (threadIdx.x == 0) {
        float t = 0.f;
        #pragma unroll
        for (int i = 0; i < 8; i++) t += sh[i];
        sh[0] = t;
    }
    __syncthreads();
    return sh[0];
}
__device__ __forceinline__ float bmax(float v, float* sh) {
    #pragma unroll
    for (int o = 16; o; o >>= 1) v = fmaxf(v, __shfl_xor_sync(0xffffffffu, v, o));
    __syncthreads();
    if ((threadIdx.x & 31) == 0) sh[threadIdx.x >> 5] = v;
    __syncthreads();
    if (threadIdx.x == 0) {
        float t = sh[0];
        #pragma unroll
        for (int i = 1; i < 8; i++) t = fmaxf(t, sh[i]);
        sh[0] = t;
    }
    __syncthreads();
    return sh[0];
}

// ======================= 0) fp32 -> split bf16 =======================
__global__ __launch_bounds__(256)
void convert_kernel(const float* __restrict__ enc, const float* __restrict__ W) {
    const int NA4 = NB * TT * CC / 4;
    const int NW4 = 2048 * CC / 4;
    int i = blockIdx.x * 256 + threadIdx.x;
    float4 v;
    __nv_bfloat16* hid;
    __nv_bfloat16* lod;
    size_t o4;
    if (i < NA4) {
        v = ((const float4*)enc)[i];
        hid = g_Ahi; lod = g_Alo; o4 = (size_t)i * 4;
    } else if (i < NA4 + NW4) {
        int j = i - NA4;
        int row = j >> 7;
        if (row < VV) v = ((const float4*)W)[j];
        else          v = make_float4(0.f, 0.f, 0.f, 0.f);
        hid = g_Whi; lod = g_Wlo; o4 = (size_t)j * 4;
    } else return;

    float a[4] = {v.x, v.y, v.z, v.w};
    union { __nv_bfloat16 b[4]; uint2 u; } H, L;
    #pragma unroll
    for (int k = 0; k < 4; k++) {
        H.b[k] = __float2bfloat16_rn(a[k]);
        L.b[k] = __float2bfloat16_rn(a[k] - __bfloat162float(H.b[k]));
    }
    *(uint2*)(hid + o4) = H.u;
    *(uint2*)(lod + o4) = L.u;
}

// ======================= 1) HMMA GEMM (mma.sync bf16, split-bf16 x3) =======================
__device__ __forceinline__ void issue_stage(int rm0, int v0, int k0, uint32_t stb) {
    const int tid = threadIdx.x;
    #pragma unroll
    for (int j = 0; j < 8; j++) {
        const int g = tid + j * 256;
        const int plane = g >> 9;
        const int idx = g & 511;
        const int row = idx >> 2;
        const int cch = idx & 3;
        const __nv_bfloat16* sp;
        int grow;
        if (plane == 0)      { sp = g_Ahi; grow = rm0 + row; }
        else if (plane == 1) { sp = g_Alo; grow = rm0 + row; }
        else if (plane == 2) { sp = g_Whi; grow = v0 + row; }
        else                 { sp = g_Wlo; grow = v0 + row; }
        uint32_t dst = stb + plane * PLANE_B + row * ROWB + cch * 16;
        cp_async16(dst, sp + (size_t)grow * CC + k0 + cch * 8);
    }
    cp_commit();
}

__global__ __launch_bounds__(256, 2)
void gemm_hmma_kernel(const int* __restrict__ lens, const float* __restrict__ bias) {
    const int v0  = blockIdx.x * BNg;
    const int rm0 = blockIdx.y * BMg;
    {
        int b_first = rm0 / TT, b_last = (rm0 + BMg - 1) / TT;
        bool act = false;
        for (int b = b_first; b <= b_last && b < NB; b++) {
            int t_lo = max(rm0, b * TT) - b * TT;
            if (t_lo < lens[b]) act = true;
        }
        if (!act) return;
    }
    extern __shared__ char smem[];
    const uint32_t sb = s2u(smem);
    const int tid = threadIdx.x;
    const int lane = tid & 31;
    const int wid = tid >> 5;
    const int wm = wid >> 2;
    const int wn = wid & 3;

    const uint32_t abase = (uint32_t)((wm * 64 + (lane & 15)) * ROWB + (lane >> 4) * 16);
    const int n_l = (lane & 7) + ((lane >> 4) << 3);
    const uint32_t bbase = (uint32_t)((wn * 32 + n_l) * ROWB + ((lane >> 3) & 1) * 16);

    float acc[4][4][4];
    #pragma unroll
    for (int i = 0; i < 4; i++)
        #pragma unroll
        for (int j = 0; j < 4; j++)
            #pragma unroll
            for (int q = 0; q < 4; q++) acc[i][j][q] = 0.f;

    issue_stage(rm0, v0, 0, sb);

    for (int kt = 0; kt < NSTG; kt++) {
        const uint32_t stb = sb + (kt & 1) * STAGE_B;
        if (kt + 1 < NSTG) {
            issue_stage(rm0, v0, (kt + 1) * BKg, sb + ((kt + 1) & 1) * STAGE_B);
            cp_wait<1>();
        } else {
            cp_wait<0>();
        }
        __syncthreads();

        #pragma unroll
        for (int ks = 0; ks < 2; ks++) {
            uint32_t bh[4][2], bl[4][2];
            #pragma unroll
            for (int pr = 0; pr < 2; pr++) {
                uint32_t addr = stb + 2 * PLANE_B + bbase + pr * (16 * ROWB) + ks * 32;
                ldsm4(bh[pr * 2][0], bh[pr * 2][1], bh[pr * 2 + 1][0], bh[pr * 2 + 1][1], addr);
                addr += PLANE_B;
                ldsm4(bl[pr * 2][0], bl[pr * 2][1], bl[pr * 2 + 1][0], bl[pr * 2 + 1][1], addr);
            }
            #pragma unroll
            for (int mt = 0; mt < 4; mt++) {
                uint32_t ah[4], alo[4];
                uint32_t addr = stb + abase + mt * (16 * ROWB) + ks * 32;
                ldsm4(ah[0], ah[1], ah[2], ah[3], addr);
                ldsm4(alo[0], alo[1], alo[2], alo[3], addr + PLANE_B);
                #pragma unroll
                for (int nt = 0; nt < 4; nt++) {
                    mma16816(acc[mt][nt], ah,  bh[nt]);
                    mma16816(acc[mt][nt], alo, bh[nt]);
                    mma16816(acc[mt][nt], ah,  bl[nt]);
                }
            }
        }
        __syncthreads();
    }

    const int r0 = rm0 + wm * 64 + (lane >> 2);
    const int c0 = v0 + wn * 32 + (lane & 3) * 2;
    #pragma unroll
    for (int nt = 0; nt < 4; nt++) {
        const int col = c0 + nt * 8;
        if (col < VV) {
            const float b0 = bias[col], b1 = bias[col + 1];
            #pragma unroll
            for (int mt = 0; mt < 4; mt++) {
                const int row = r0 + mt * 16;
                float* d = g_logits + (size_t)row * VV + col;
                float2 o0 = make_float2(acc[mt][nt][0] + b0, acc[mt][nt][1] + b1);
                float2 o1 = make_float2(acc[mt][nt][2] + b0, acc[mt][nt][3] + b1);
                *(float2*)d = o0;
                *(float2*)(d + 8 * VV) = o1;
            }
        }
    }
}

// ======================= 2) softmax + KL + ext log2-prob gather =======================
__global__ __launch_bounds__(256)
void softmax_kl_kernel(const int* __restrict__ lens, const int* __restrict__ targets) {
    __shared__ float sh[8];
    const int t = blockIdx.x;
    const int p = blockIdx.y;
    const int tid = threadIdx.x;
    const int pb = p * TT + t;

    if (t >= lens[p]) {
        if (tid == 0) g_kl[pb] = 0.f;
        return;
    }
    const size_t r1 = (size_t)p * TT + t;
    const size_t r2 = (size_t)(p + NPAIR) * TT + t;
    const float* L1 = g_logits + r1 * VV;
    const float* L2 = g_logits + r2 * VV;
    const float4* L1v = (const float4*)L1;
    const float4* L2v = (const float4*)L2;

    float v1[2][4], v2[2][4];
    float m1 = -3.4e38f, m2 = -3.4e38f;
    #pragma unroll
    for (int q = 0; q < 2; q++) {
        int i = tid + q * 256;
        if (i < 500) {
            float4 a = L1v[i], b = L2v[i];
            v1[q][0] = a.x; v1[q][1] = a.y; v1[q][2] = a.z; v1[q][3] = a.w;
            v2[q][0] = b.x; v2[q][1] = b.y; v2[q][2] = b.z; v2[q][3] = b.w;
            #pragma unroll
            for (int k = 0; k < 4; k++) {
                m1 = fmaxf(m1, v1[q][k]);
                m2 = fmaxf(m2, v2[q][k]);
            }
        }
    }
    m1 = bmax(m1, sh);
    m2 = bmax(m2, sh);

    float e1[2][4], e2[2][4];
    float s1 = 0.f, s2 = 0.f;
    #pragma unroll
    for (int q = 0; q < 2; q++) {
        int i = tid + q * 256;
        if (i < 500) {
            #pragma unroll
            for (int k = 0; k < 4; k++) {
                e1[q][k] = __expf(v1[q][k] - m1); s1 += e1[q][k];
                e2[q][k] = __expf(v2[q][k] - m2); s2 += e2[q][k];
            }
        }
    }
    const float Z1 = bsum(s1, sh);
    const float Z2 = bsum(s2, sh);
    const float lZ1 = __logf(Z1), lZ2 = __logf(Z2);
    const float iZ1 = 1.f / Z1,   iZ2 = 1.f / Z2;

    float kl = 0.f;
    #pragma unroll
    for (int q = 0; q < 2; q++) {
        int i = tid + q * 256;
        if (i < 500) {
            #pragma unroll
            for (int k = 0; k < 4; k++) {
                float p1 = v1[q][k] - m1 - lZ1;
                float p2 = v2[q][k] - m2 - lZ2;
                kl += (p1 - p2) * (e1[q][k] * iZ1 - e2[q][k] * iZ2);
            }
        }
    }
    kl = bsum(kl, sh);
    if (tid == 0) g_kl[pb] = kl;

    if (tid < 1 + UU) {
        int c = (tid == 0) ? 0 : targets[p * UU + (tid - 1)];
        g_lp[r1 * EXT + tid] = (L1[c] - m1 - lZ1) * LOG2E;
        g_lp[r2 * EXT + tid] = (L2[c] - m2 - lZ2) * LOG2E;
    }
}

// ======================= 3) CTC forward (log2, 2 time steps per sync) =======================
// mode: -1 invalid state, 0 = self only (s==0), 1 = 2-term, 2 = 3-term
__device__ __forceinline__ int ctc_mode(int sp, const int* tg) {
    if (sp < 0 || sp >= SS) return -1;
    if (sp == 0) return 0;
    if ((sp & 1) && sp >= 3) {
        int u = (sp - 1) >> 1;
        if (tg[u] != tg[u - 1]) return 2;
    }
    return 1;
}
__device__ __forceinline__ float ctc_step(int mode, float a0, float a1, float a2) {
    if (mode == 2) {
        float m = fmaxf(a0, fmaxf(a1, a2));
        float r = exp2f(a0 - m) + exp2f(a1 - m) + exp2f(a2 - m);
        return m + log2f(r);
    }
    if (mode == 1) {
        float m = fmaxf(a0, a1);
        float d = fminf(a0, a1) - m;
        return m + log2f(1.0f + exp2f(d));
    }
    return a0;
}

__global__ __launch_bounds__(224, 1)
void ctc_kernel(const int* __restrict__ lens, const int* __restrict__ targets,
                const int* __restrict__ tlens) {
    const int b = blockIdx.x;
    const int tid = threadIdx.x;
    const int lane = tid & 31;
    const int wid = tid >> 5;
    const int len = lens[b];
    const int* tg = targets + b * UU;

    const int s = tid;
    const int mode0 = ctc_mode(s, tg);
    const int mode1 = ctc_mode(s - 1, tg);
    const int mode2 = ctc_mode(s - 2, tg);
    const int pidx = (s & 1) ? min(1 + ((s - 1) >> 1), EXT - 1) : 0;

    __shared__ float bnd[2][7][4];        // prev-warp alphas: lanes 28..31
    __shared__ float lpb[2][7][2][16];    // prev-warp lp: [parity][warp][lane30/31][step]
    __shared__ float al[SS + 1];

    const float* base = g_lp + (size_t)b * TT * EXT;
    const int nchunk = (len + 15) >> 4;

    float pc[16], pn[16];
    #pragma unroll
    for (int j = 0; j < 16; j++) {
        pc[j] = (j < len) ? __ldg(base + (size_t)j * EXT + pidx) : 0.f;
        if (lane >= 30) lpb[0][wid][lane - 30][j] = pc[j];
    }

    float a = NEGF;
    if (s == 0 || s == 1) a = pc[0];
    if (lane >= 28) bnd[0][wid][lane - 28] = a;
    __syncthreads();

    int rb = 0;   // read-buffer parity for bnd
    for (int c = 0; c < nchunk; c++) {
        const int cp = c & 1;
        if (c + 1 < nchunk) {
            const int tn0 = (c + 1) * 16;
            #pragma unroll
            for (int j = 0; j < 16; j++) {
                int t = tn0 + j;
                pn[j] = (t < len) ? __ldg(base + (size_t)t * EXT + pidx) : 0.f;
                if (lane >= 30) lpb[cp ^ 1][wid][lane - 30][j] = pn[j];
            }
        }
        #pragma unroll
        for (int jj = 1; jj < 16; jj += 2) {
            const int t = 16 * c + jj;
            if (t >= len) break;
            const bool full = (t + 1 < len);

            // gather neighbor alphas at t-1
            float am1 = __shfl_up_sync(0xffffffffu, a, 1);
            float am2 = __shfl_up_sync(0xffffffffu, a, 2);
            float am3 = __shfl_up_sync(0xffffffffu, a, 3);
            float am4 = __shfl_up_sync(0xffffffffu, a, 4);
            if (lane < 4) {
                if (wid > 0) {
                    const float* B = bnd[rb][wid - 1];
                    if (lane < 1) am1 = B[3];
                    if (lane < 2) am2 = B[2 + lane];
                    if (lane < 3) am3 = B[1 + lane];
                    am4 = B[lane];
                } else {
                    if (lane < 1) am1 = NEGF;
                    if (lane < 2) am2 = NEGF;
                    if (lane < 3) am3 = NEGF;
                    am4 = NEGF;
                }
            }

            float anew;
            const float lp_s = pc[jj];
            if (full) {
                // neighbor lp at time t
                float lp1 = __shfl_up_sync(0xffffffffu, lp_s, 1);
                float lp2v = __shfl_up_sync(0xffffffffu, lp_s, 2);
                if (lane < 2 && wid > 0) {
                    if (lane == 0) {
                        lp1  = lpb[cp][wid - 1][1][jj];
                        lp2v = lpb[cp][wid - 1][0][jj];
                    } else {
                        lp2v = lpb[cp][wid - 1][1][jj];
                    }
                }
                const float lp_nx = (jj + 1 < 16) ? pc[jj + 1] : pn[0];
                // alphas at t for s, s-1, s-2 (redundant compute)
                float b0 = (mode0 < 0) ? NEGF : ctc_step(mode0, a,   am1, am2) + lp_s;
                float b1 = (mode1 < 0) ? NEGF : ctc_step(mode1, am1, am2, am3) + lp1;
                float b2 = (mode2 < 0) ? NEGF : ctc_step(mode2, am2, am3, am4) + lp2v;
                // own alpha at t+1
                anew = (mode0 < 0) ? NEGF : ctc_step(mode0, b0, b1, b2) + lp_nx;
            } else {
                anew = (mode0 < 0) ? NEGF : ctc_step(mode0, a, am1, am2) + lp_s;
            }
            if (lane >= 28) bnd[rb ^ 1][wid][lane - 28] = anew;
            rb ^= 1;
            a = anew;
            __syncthreads();
        }
        if (c + 1 < nchunk) {
            #pragma unroll
            for (int j = 0; j < 16; j++) pc[j] = pn[j];
        }
    }

    if (s < SS) al[s] = a;
    __syncthreads();
    if (tid == 0) {
        const int e = 2 * tlens[b];
        const float ab = al[e], alb = al[e - 1];
        const float m = fmaxf(ab, alb);
        const float lse2 = m + log2f(exp2f(ab - m) + exp2f(alb - m));
        g_ctc[b] = (float)(-(double)lse2 * LN2);
    }
}

// ======================= 4) final reduction =======================
__global__ __launch_bounds__(256)
void reduce_kernel(float* __restrict__ out) {
    __shared__ float sh[8];
    const int tid = threadIdx.x;
    float skl = 0.f;
    for (int i = tid; i < NPAIR * TT; i += 256) skl += g_kl[i];
    float sctc = (tid < NB) ? g_ctc[tid] : 0.f;
    skl = bsum(skl, sh);
    sctc = bsum(sctc, sh);
    if (tid == 0) {
        out[0] = 0.5f * sctc;
        out[1] = 0.5f * skl;
    }
}

extern "C" void kernel_launch(void* const* d_in, const int* in_sizes, int n_in,
                              void* d_out, int out_size) {
    const float* enc     = (const float*)d_in[0];
    const float* W       = (const float*)d_in[1];
    const float* bias    = (const float*)d_in[2];
    const int*   lens    = (const int*)d_in[3];
    const int*   targets = (const int*)d_in[4];
    const int*   tlens   = (const int*)d_in[5];
    float* out = (float*)d_out;

    cudaFuncSetAttribute(gemm_hmma_kernel, cudaFuncAttributeMaxDynamicSharedMemorySize, GEMM_SMEM);

    const int NA4 = NB * TT * CC / 4;
    const int NW4 = 2048 * CC / 4;
    convert_kernel<<<(NA4 + NW4 + 255) / 256, 256>>>(enc, W);

    dim3 gg((VV + BNg - 1) / BNg, (NB * TT) / BMg);
    gemm_hmma_kernel<<<gg, 256, GEMM_SMEM>>>(lens, bias);

    dim3 g2(TT, NPAIR);
    softmax_kl_kernel<<<g2, 256>>>(lens, targets);

    ctc_kernel<<<NB, 224>>>(lens, targets, tlens);

    reduce_kernel<<<1, 256>>>(out);
}

// round 9
// speedup vs baseline: 1.8528x; 1.8528x over previous
#include <cuda_runtime.h>
#include <cuda_bf16.h>
#include <math.h>
#include <stdint.h>

#define TT   1000
#define NB   32
#define NPAIR 16
#define VV   2000
#define CC   512
#define UU   100
#define SS   201
#define EXT  104
#define NEGF (-1.0e30f)

#define BMg 128
#define BNg 128
#define BKg 32
#define NSTG (CC / BKg)
#define ROWB 80
#define PLANE_B (BMg * ROWB)
#define STAGE_B (4 * PLANE_B)
#define GEMM_SMEM (2 * STAGE_B)

__device__ float g_logits[(size_t)NB * TT * VV];
__device__ float g_lp[(size_t)NB * TT * EXT];   // natural-log probs at ext classes
__device__ float g_kl[NPAIR * TT];
__device__ float g_ctc[NB];
__device__ __nv_bfloat16 g_Ahi[(size_t)NB * TT * CC];
__device__ __nv_bfloat16 g_Alo[(size_t)NB * TT * CC];
__device__ __nv_bfloat16 g_Whi[(size_t)2048 * CC];
__device__ __nv_bfloat16 g_Wlo[(size_t)2048 * CC];

__device__ __forceinline__ uint32_t s2u(const void* p) {
    uint32_t a;
    asm("{ .reg .u64 t; cvta.to.shared.u64 t, %1; cvt.u32.u64 %0, t; }" : "=r"(a) : "l"(p));
    return a;
}
__device__ __forceinline__ void cp_async16(uint32_t dst, const void* src) {
    asm volatile("cp.async.cg.shared.global [%0], [%1], 16;" :: "r"(dst), "l"(src) : "memory");
}
__device__ __forceinline__ void cp_commit() {
    asm volatile("cp.async.commit_group;" ::: "memory");
}
template <int N>
__device__ __forceinline__ void cp_wait() {
    asm volatile("cp.async.wait_group %0;" :: "n"(N) : "memory");
}
__device__ __forceinline__ void ldsm4(uint32_t& r0, uint32_t& r1, uint32_t& r2, uint32_t& r3,
                                      uint32_t a) {
    asm volatile("ldmatrix.sync.aligned.m8n8.x4.shared.b16 {%0,%1,%2,%3}, [%4];"
                 : "=r"(r0), "=r"(r1), "=r"(r2), "=r"(r3) : "r"(a));
}
__device__ __forceinline__ void mma16816(float* c, const uint32_t* a, const uint32_t* b) {
    asm volatile(
        "mma.sync.aligned.m16n8k16.row.col.f32.bf16.bf16.f32 "
        "{%0,%1,%2,%3}, {%4,%5,%6,%7}, {%8,%9}, {%0,%1,%2,%3};"
        : "+f"(c[0]), "+f"(c[1]), "+f"(c[2]), "+f"(c[3])
        : "r"(a[0]), "r"(a[1]), "r"(a[2]), "r"(a[3]), "r"(b[0]), "r"(b[1]));
}

__device__ __forceinline__ float bsum(float v, float* sh) {
    #pragma unroll
    for (int o = 16; o; o >>= 1) v += __shfl_xor_sync(0xffffffffu, v, o);
    __syncthreads();
    if ((threadIdx.x & 31) == 0) sh[threadIdx.x >> 5] = v;
    __syncthreads();
    if (threadIdx.x == 0) {
        float t = 0.f;
        #pragma unroll
        for (int i = 0; i < 8; i++) t += sh[i];
        sh[0] = t;
    }
    __syncthreads();
    return sh[0];
}
__device__ __forceinline__ float bmax(float v, float* sh) {
    #pragma unroll
    for (int o = 16; o; o >>= 1) v = fmaxf(v, __shfl_xor_sync(0xffffffffu, v, o));
    __syncthreads();
    if ((threadIdx.x & 31) == 0) sh[threadIdx.x >> 5] = v;
    __syncthreads();
    if (threadIdx.x == 0) {
        float t = sh[0];
        #pragma unroll
        for (int i = 1; i < 8; i++) t = fmaxf(t, sh[i]);
        sh[0] = t;
    }
    __syncthreads();
    return sh[0];
}

// ======================= 0) fp32 -> split bf16 =======================
__global__ __launch_bounds__(256)
void convert_kernel(const float* __restrict__ enc, const float* __restrict__ W) {
    const int NA4 = NB * TT * CC / 4;
    const int NW4 = 2048 * CC / 4;
    int i = blockIdx.x * 256 + threadIdx.x;
    float4 v;
    __nv_bfloat16* hid;
    __nv_bfloat16* lod;
    size_t o4;
    if (i < NA4) {
        v = ((const float4*)enc)[i];
        hid = g_Ahi; lod = g_Alo; o4 = (size_t)i * 4;
    } else if (i < NA4 + NW4) {
        int j = i - NA4;
        int row = j >> 7;
        if (row < VV) v = ((const float4*)W)[j];
        else          v = make_float4(0.f, 0.f, 0.f, 0.f);
        hid = g_Whi; lod = g_Wlo; o4 = (size_t)j * 4;
    } else return;

    float a[4] = {v.x, v.y, v.z, v.w};
    union { __nv_bfloat16 b[4]; uint2 u; } H, L;
    #pragma unroll
    for (int k = 0; k < 4; k++) {
        H.b[k] = __float2bfloat16_rn(a[k]);
        L.b[k] = __float2bfloat16_rn(a[k] - __bfloat162float(H.b[k]));
    }
    *(uint2*)(hid + o4) = H.u;
    *(uint2*)(lod + o4) = L.u;
}

// ======================= 1) HMMA GEMM (mma.sync bf16, split-bf16 x3) =======================
__device__ __forceinline__ void issue_stage(int rm0, int v0, int k0, uint32_t stb) {
    const int tid = threadIdx.x;
    #pragma unroll
    for (int j = 0; j < 8; j++) {
        const int g = tid + j * 256;
        const int plane = g >> 9;
        const int idx = g & 511;
        const int row = idx >> 2;
        const int cch = idx & 3;
        const __nv_bfloat16* sp;
        int grow;
        if (plane == 0)      { sp = g_Ahi; grow = rm0 + row; }
        else if (plane == 1) { sp = g_Alo; grow = rm0 + row; }
        else if (plane == 2) { sp = g_Whi; grow = v0 + row; }
        else                 { sp = g_Wlo; grow = v0 + row; }
        uint32_t dst = stb + plane * PLANE_B + row * ROWB + cch * 16;
        cp_async16(dst, sp + (size_t)grow * CC + k0 + cch * 8);
    }
    cp_commit();
}

__global__ __launch_bounds__(256, 2)
void gemm_hmma_kernel(const int* __restrict__ lens, const float* __restrict__ bias) {
    const int v0  = blockIdx.x * BNg;
    const int rm0 = blockIdx.y * BMg;
    {
        int b_first = rm0 / TT, b_last = (rm0 + BMg - 1) / TT;
        bool act = false;
        for (int b = b_first; b <= b_last && b < NB; b++) {
            int t_lo = max(rm0, b * TT) - b * TT;
            if (t_lo < lens[b]) act = true;
        }
        if (!act) return;
    }
    extern __shared__ char smem[];
    const uint32_t sb = s2u(smem);
    const int tid = threadIdx.x;
    const int lane = tid & 31;
    const int wid = tid >> 5;
    const int wm = wid >> 2;
    const int wn = wid & 3;

    const uint32_t abase = (uint32_t)((wm * 64 + (lane & 15)) * ROWB + (lane >> 4) * 16);
    const int n_l = (lane & 7) + ((lane >> 4) << 3);
    const uint32_t bbase = (uint32_t)((wn * 32 + n_l) * ROWB + ((lane >> 3) & 1) * 16);

    float acc[4][4][4];
    #pragma unroll
    for (int i = 0; i < 4; i++)
        #pragma unroll
        for (int j = 0; j < 4; j++)
            #pragma unroll
            for (int q = 0; q < 4; q++) acc[i][j][q] = 0.f;

    issue_stage(rm0, v0, 0, sb);

    for (int kt = 0; kt < NSTG; kt++) {
        const uint32_t stb = sb + (kt & 1) * STAGE_B;
        if (kt + 1 < NSTG) {
            issue_stage(rm0, v0, (kt + 1) * BKg, sb + ((kt + 1) & 1) * STAGE_B);
            cp_wait<1>();
        } else {
            cp_wait<0>();
        }
        __syncthreads();

        #pragma unroll
        for (int ks = 0; ks < 2; ks++) {
            uint32_t bh[4][2], bl[4][2];
            #pragma unroll
            for (int pr = 0; pr < 2; pr++) {
                uint32_t addr = stb + 2 * PLANE_B + bbase + pr * (16 * ROWB) + ks * 32;
                ldsm4(bh[pr * 2][0], bh[pr * 2][1], bh[pr * 2 + 1][0], bh[pr * 2 + 1][1], addr);
                addr += PLANE_B;
                ldsm4(bl[pr * 2][0], bl[pr * 2][1], bl[pr * 2 + 1][0], bl[pr * 2 + 1][1], addr);
            }
            #pragma unroll
            for (int mt = 0; mt < 4; mt++) {
                uint32_t ah[4], alo[4];
                uint32_t addr = stb + abase + mt * (16 * ROWB) + ks * 32;
                ldsm4(ah[0], ah[1], ah[2], ah[3], addr);
                ldsm4(alo[0], alo[1], alo[2], alo[3], addr + PLANE_B);
                #pragma unroll
                for (int nt = 0; nt < 4; nt++) {
                    mma16816(acc[mt][nt], ah,  bh[nt]);
                    mma16816(acc[mt][nt], alo, bh[nt]);
                    mma16816(acc[mt][nt], ah,  bl[nt]);
                }
            }
        }
        __syncthreads();
    }

    const int r0 = rm0 + wm * 64 + (lane >> 2);
    const int c0 = v0 + wn * 32 + (lane & 3) * 2;
    #pragma unroll
    for (int nt = 0; nt < 4; nt++) {
        const int col = c0 + nt * 8;
        if (col < VV) {
            const float b0 = bias[col], b1 = bias[col + 1];
            #pragma unroll
            for (int mt = 0; mt < 4; mt++) {
                const int row = r0 + mt * 16;
                float* d = g_logits + (size_t)row * VV + col;
                float2 o0 = make_float2(acc[mt][nt][0] + b0, acc[mt][nt][1] + b1);
                float2 o1 = make_float2(acc[mt][nt][2] + b0, acc[mt][nt][3] + b1);
                *(float2*)d = o0;
                *(float2*)(d + 8 * VV) = o1;
            }
        }
    }
}

// ======================= 2) softmax + KL + ext log-prob gather =======================
__global__ __launch_bounds__(256)
void softmax_kl_kernel(const int* __restrict__ lens, const int* __restrict__ targets) {
    __shared__ float sh[8];
    const int t = blockIdx.x;
    const int p = blockIdx.y;
    const int tid = threadIdx.x;
    const int pb = p * TT + t;

    if (t >= lens[p]) {
        if (tid == 0) g_kl[pb] = 0.f;
        return;
    }
    const size_t r1 = (size_t)p * TT + t;
    const size_t r2 = (size_t)(p + NPAIR) * TT + t;
    const float* L1 = g_logits + r1 * VV;
    const float* L2 = g_logits + r2 * VV;
    const float4* L1v = (const float4*)L1;
    const float4* L2v = (const float4*)L2;

    float v1[2][4], v2[2][4];
    float m1 = -3.4e38f, m2 = -3.4e38f;
    #pragma unroll
    for (int q = 0; q < 2; q++) {
        int i = tid + q * 256;
        if (i < 500) {
            float4 a = L1v[i], b = L2v[i];
            v1[q][0] = a.x; v1[q][1] = a.y; v1[q][2] = a.z; v1[q][3] = a.w;
            v2[q][0] = b.x; v2[q][1] = b.y; v2[q][2] = b.z; v2[q][3] = b.w;
            #pragma unroll
            for (int k = 0; k < 4; k++) {
                m1 = fmaxf(m1, v1[q][k]);
                m2 = fmaxf(m2, v2[q][k]);
            }
        }
    }
    m1 = bmax(m1, sh);
    m2 = bmax(m2, sh);

    float e1[2][4], e2[2][4];
    float s1 = 0.f, s2 = 0.f;
    #pragma unroll
    for (int q = 0; q < 2; q++) {
        int i = tid + q * 256;
        if (i < 500) {
            #pragma unroll
            for (int k = 0; k < 4; k++) {
                e1[q][k] = __expf(v1[q][k] - m1); s1 += e1[q][k];
                e2[q][k] = __expf(v2[q][k] - m2); s2 += e2[q][k];
            }
        }
    }
    const float Z1 = bsum(s1, sh);
    const float Z2 = bsum(s2, sh);
    const float lZ1 = __logf(Z1), lZ2 = __logf(Z2);
    const float iZ1 = 1.f / Z1,   iZ2 = 1.f / Z2;

    float kl = 0.f;
    #pragma unroll
    for (int q = 0; q < 2; q++) {
        int i = tid + q * 256;
        if (i < 500) {
            #pragma unroll
            for (int k = 0; k < 4; k++) {
                float p1 = v1[q][k] - m1 - lZ1;
                float p2 = v2[q][k] - m2 - lZ2;
                kl += (p1 - p2) * (e1[q][k] * iZ1 - e2[q][k] * iZ2);
            }
        }
    }
    kl = bsum(kl, sh);
    if (tid == 0) g_kl[pb] = kl;

    // natural-log log-probs at extended-label classes for CTC (R4 layout)
    if (tid < 1 + UU) {
        int c = (tid == 0) ? 0 : targets[p * UU + (tid - 1)];
        g_lp[r1 * EXT + tid] = L1[c] - m1 - lZ1;
        g_lp[r2 * EXT + tid] = L2[c] - m2 - lZ2;
    }
}

// ======================= 3) CTC forward (log domain, R4 design verbatim) =======================
__global__ __launch_bounds__(256, 1)
void ctc_kernel(const int* __restrict__ lens, const int* __restrict__ targets,
                const int* __restrict__ tlens) {
    const int b = blockIdx.x;
    const int tid = threadIdx.x;
    const int len = lens[b];
    const int* tg = targets + b * UU;

    const int s = tid;
    const bool isstate = (s < SS);
    const int u = (s - 1) >> 1;
    const int pidx = (s & 1) ? (1 + u) : 0;
    bool can_skip = false;
    if (isstate && (s & 1) && s >= 3) can_skip = (tg[u] != tg[u - 1]);

    __shared__ float al[2][SS + 3];
    __shared__ float lpb[2][16][EXT];

    const float* base = g_lp + (size_t)b * TT * EXT;
    const int nchunk = (len + 15) / 16;

    {
        int n0 = min(16, len) * EXT;
        for (int i = tid; i < n0; i += 256) (&lpb[0][0][0])[i] = base[i];
    }
    __syncthreads();

    if (isstate) {
        float v = NEGF;
        if (s == 0) v = lpb[0][0][0];
        if (s == 1) v = lpb[0][0][1];
        al[0][s] = v;
    }
    __syncthreads();

    int curbuf = 0;
    float stage[7];
    for (int c = 0; c < nchunk; c++) {
        int nn = 0;
        const int tn0 = (c + 1) * 16;
        if (c + 1 < nchunk) {
            nn = (min(tn0 + 16, len) - tn0) * EXT;
            #pragma unroll
            for (int q = 0; q < 7; q++) {
                int i = tid + q * 256;
                stage[q] = (i < nn) ? base[(size_t)tn0 * EXT + i] : 0.f;
            }
        }
        const int t0 = c * 16;
        const int te = min(t0 + 16, len);
        for (int t = max(t0, 1); t < te; t++) {
            if (isstate) {
                const float lp = lpb[c & 1][t - t0][pidx];
                const float a  = al[curbuf][s];
                const float bb = (s >= 1) ? al[curbuf][s - 1] : NEGF;
                const float cc = can_skip ? al[curbuf][s - 2] : NEGF;
                const float m = fmaxf(a, fmaxf(bb, cc));
                const float r = __expf(a - m) + __expf(bb - m) + __expf(cc - m);
                al[curbuf ^ 1][s] = m + __logf(r) + lp;
            }
            __syncthreads();
            curbuf ^= 1;
        }
        if (c + 1 < nchunk) {
            #pragma unroll
            for (int q = 0; q < 7; q++) {
                int i = tid + q * 256;
                if (i < nn) (&lpb[(c + 1) & 1][0][0])[i] = stage[q];
            }
        }
        __syncthreads();
    }

    if (tid == 0) {
        const int e = 2 * tlens[b];
        const float a = al[curbuf][e];
        const float bb = al[curbuf][e - 1];
        const float m = fmaxf(a, bb);
        g_ctc[b] = -(m + __logf(__expf(a - m) + __expf(bb - m)));
    }
}

// ======================= 4) final reduction =======================
__global__ __launch_bounds__(256)
void reduce_kernel(float* __restrict__ out) {
    __shared__ float sh[8];
    const int tid = threadIdx.x;
    float skl = 0.f;
    for (int i = tid; i < NPAIR * TT; i += 256) skl += g_kl[i];
    float sctc = (tid < NB) ? g_ctc[tid] : 0.f;
    skl = bsum(skl, sh);
    sctc = bsum(sctc, sh);
    if (tid == 0) {
        out[0] = 0.5f * sctc;
        out[1] = 0.5f * skl;
    }
}

extern "C" void kernel_launch(void* const* d_in, const int* in_sizes, int n_in,
                              void* d_out, int out_size) {
    const float* enc     = (const float*)d_in[0];
    const float* W       = (const float*)d_in[1];
    const float* bias    = (const float*)d_in[2];
    const int*   lens    = (const int*)d_in[3];
    const int*   targets = (const int*)d_in[4];
    const int*   tlens   = (const int*)d_in[5];
    float* out = (float*)d_out;

    cudaFuncSetAttribute(gemm_hmma_kernel, cudaFuncAttributeMaxDynamicSharedMemorySize, GEMM_SMEM);

    const int NA4 = NB * TT * CC / 4;
    const int NW4 = 2048 * CC / 4;
    convert_kernel<<<(NA4 + NW4 + 255) / 256, 256>>>(enc, W);

    dim3 gg((VV + BNg - 1) / BNg, (NB * TT) / BMg);
    gemm_hmma_kernel<<<gg, 256, GEMM_SMEM>>>(lens, bias);

    dim3 g2(TT, NPAIR);
    softmax_kl_kernel<<<g2, 256>>>(lens, targets);

    ctc_kernel<<<NB, 256>>>(lens, targets, tlens);

    reduce_kernel<<<1, 256>>>(out);
}

// round 10
// speedup vs baseline: 2.2531x; 1.2161x over previous
#include <cuda_runtime.h>
#include <cuda_fp16.h>
#include <math.h>
#include <stdint.h>

#define TT   1000
#define NB   32
#define NPAIR 16
#define VV   2000
#define CC   512
#define UU   100
#define SS   201
#define EXT  104
#define NEGF (-1.0e30f)

#define BMg 128
#define BNg 128
#define BKg 32
#define NSTG (CC / BKg)
#define ROWB 80
#define PLANE_B (BMg * ROWB)      // 10240
#define STAGE_B (3 * PLANE_B)     // Ah, Al, Wh
#define GEMM_SMEM (2 * STAGE_B)   // 61440

__device__ float g_logits[(size_t)NB * TT * VV];
__device__ float g_lp[(size_t)NB * TT * EXT];   // natural-log probs at ext classes
__device__ float g_kl[NPAIR * TT];
__device__ float g_ctc[NB];
__device__ __half g_Ah[(size_t)NB * TT * CC];
__device__ __half g_Al[(size_t)NB * TT * CC];
__device__ __half g_Wh[(size_t)2048 * CC];      // vocab padded to 2048 rows

__device__ __forceinline__ uint32_t s2u(const void* p) {
    uint32_t a;
    asm("{ .reg .u64 t; cvta.to.shared.u64 t, %1; cvt.u32.u64 %0, t; }" : "=r"(a) : "l"(p));
    return a;
}
__device__ __forceinline__ void cp_async16(uint32_t dst, const void* src) {
    asm volatile("cp.async.cg.shared.global [%0], [%1], 16;" :: "r"(dst), "l"(src) : "memory");
}
__device__ __forceinline__ void cp_commit() {
    asm volatile("cp.async.commit_group;" ::: "memory");
}
template <int N>
__device__ __forceinline__ void cp_wait() {
    asm volatile("cp.async.wait_group %0;" :: "n"(N) : "memory");
}
__device__ __forceinline__ void ldsm4(uint32_t& r0, uint32_t& r1, uint32_t& r2, uint32_t& r3,
                                      uint32_t a) {
    asm volatile("ldmatrix.sync.aligned.m8n8.x4.shared.b16 {%0,%1,%2,%3}, [%4];"
                 : "=r"(r0), "=r"(r1), "=r"(r2), "=r"(r3) : "r"(a));
}
__device__ __forceinline__ void mma16816h(float* c, const uint32_t* a, const uint32_t* b) {
    asm volatile(
        "mma.sync.aligned.m16n8k16.row.col.f32.f16.f16.f32 "
        "{%0,%1,%2,%3}, {%4,%5,%6,%7}, {%8,%9}, {%0,%1,%2,%3};"
        : "+f"(c[0]), "+f"(c[1]), "+f"(c[2]), "+f"(c[3])
        : "r"(a[0]), "r"(a[1]), "r"(a[2]), "r"(a[3]), "r"(b[0]), "r"(b[1]));
}

// ---- block reductions (single and paired) ----
__device__ __forceinline__ float bsum(float v, float* sh) {
    #pragma unroll
    for (int o = 16; o; o >>= 1) v += __shfl_xor_sync(0xffffffffu, v, o);
    __syncthreads();
    if ((threadIdx.x & 31) == 0) sh[threadIdx.x >> 5] = v;
    __syncthreads();
    if (threadIdx.x == 0) {
        float t = 0.f;
        #pragma unroll
        for (int i = 0; i < 8; i++) t += sh[i];
        sh[0] = t;
    }
    __syncthreads();
    return sh[0];
}
__device__ __forceinline__ void bmax2(float& x, float& y, float* sh) {
    #pragma unroll
    for (int o = 16; o; o >>= 1) {
        x = fmaxf(x, __shfl_xor_sync(0xffffffffu, x, o));
        y = fmaxf(y, __shfl_xor_sync(0xffffffffu, y, o));
    }
    __syncthreads();
    if ((threadIdx.x & 31) == 0) {
        sh[(threadIdx.x >> 5) * 2]     = x;
        sh[(threadIdx.x >> 5) * 2 + 1] = y;
    }
    __syncthreads();
    if (threadIdx.x == 0) {
        float tx = sh[0], ty = sh[1];
        #pragma unroll
        for (int i = 1; i < 8; i++) {
            tx = fmaxf(tx, sh[i * 2]);
            ty = fmaxf(ty, sh[i * 2 + 1]);
        }
        sh[0] = tx; sh[1] = ty;
    }
    __syncthreads();
    x = sh[0]; y = sh[1];
}
__device__ __forceinline__ void bsum2(float& x, float& y, float* sh) {
    #pragma unroll
    for (int o = 16; o; o >>= 1) {
        x += __shfl_xor_sync(0xffffffffu, x, o);
        y += __shfl_xor_sync(0xffffffffu, y, o);
    }
    __syncthreads();
    if ((threadIdx.x & 31) == 0) {
        sh[(threadIdx.x >> 5) * 2]     = x;
        sh[(threadIdx.x >> 5) * 2 + 1] = y;
    }
    __syncthreads();
    if (threadIdx.x == 0) {
        float tx = 0.f, ty = 0.f;
        #pragma unroll
        for (int i = 0; i < 8; i++) {
            tx += sh[i * 2];
            ty += sh[i * 2 + 1];
        }
        sh[0] = tx; sh[1] = ty;
    }
    __syncthreads();
    x = sh[0]; y = sh[1];
}

// ======================= 0) fp32 -> fp16 split (A) / fp16 round (W) =======================
__global__ __launch_bounds__(256)
void convert_kernel(const float* __restrict__ enc, const float* __restrict__ W) {
    const int NA4 = NB * TT * CC / 4;
    const int NW4 = 2048 * CC / 4;
    int i = blockIdx.x * 256 + threadIdx.x;
    if (i < NA4) {
        float4 v = ((const float4*)enc)[i];
        float a[4] = {v.x, v.y, v.z, v.w};
        union { __half h[4]; uint2 u; } H, L;
        #pragma unroll
        for (int k = 0; k < 4; k++) {
            H.h[k] = __float2half_rn(a[k]);
            L.h[k] = __float2half_rn(a[k] - __half2float(H.h[k]));
        }
        *(uint2*)(g_Ah + (size_t)i * 4) = H.u;
        *(uint2*)(g_Al + (size_t)i * 4) = L.u;
    } else if (i < NA4 + NW4) {
        int j = i - NA4;
        int row = j >> 7;
        float4 v = (row < VV) ? ((const float4*)W)[j] : make_float4(0.f, 0.f, 0.f, 0.f);
        float a[4] = {v.x, v.y, v.z, v.w};
        union { __half h[4]; uint2 u; } H;
        #pragma unroll
        for (int k = 0; k < 4; k++) H.h[k] = __float2half_rn(a[k]);
        *(uint2*)(g_Wh + (size_t)j * 4) = H.u;
    }
}

// ======================= 1) HMMA GEMM (fp16 split-A x exact, 2 products) =======================
__device__ __forceinline__ void issue_stage(int rm0, int v0, int k0, uint32_t stb) {
    const int tid = threadIdx.x;
    #pragma unroll
    for (int j = 0; j < 6; j++) {
        const int g = tid + j * 256;          // 0..1535
        const int plane = g >> 9;             // 0:Ah 1:Al 2:Wh
        const int idx = g & 511;
        const int row = idx >> 2;
        const int cch = idx & 3;
        const __half* sp;
        int grow;
        if (plane == 0)      { sp = g_Ah; grow = rm0 + row; }
        else if (plane == 1) { sp = g_Al; grow = rm0 + row; }
        else                 { sp = g_Wh; grow = v0 + row; }
        uint32_t dst = stb + plane * PLANE_B + row * ROWB + cch * 16;
        cp_async16(dst, sp + (size_t)grow * CC + k0 + cch * 8);
    }
    cp_commit();
}

__global__ __launch_bounds__(256, 2)
void gemm_hmma_kernel(const int* __restrict__ lens, const float* __restrict__ bias) {
    const int v0  = blockIdx.x * BNg;
    const int rm0 = blockIdx.y * BMg;
    {
        int b_first = rm0 / TT, b_last = (rm0 + BMg - 1) / TT;
        bool act = false;
        for (int b = b_first; b <= b_last && b < NB; b++) {
            int t_lo = max(rm0, b * TT) - b * TT;
            if (t_lo < lens[b]) act = true;
        }
        if (!act) return;
    }
    extern __shared__ char smem[];
    const uint32_t sb = s2u(smem);
    const int tid = threadIdx.x;
    const int lane = tid & 31;
    const int wid = tid >> 5;
    const int wm = wid >> 2;
    const int wn = wid & 3;

    const uint32_t abase = (uint32_t)((wm * 64 + (lane & 15)) * ROWB + (lane >> 4) * 16);
    const int n_l = (lane & 7) + ((lane >> 4) << 3);
    const uint32_t bbase = (uint32_t)((wn * 32 + n_l) * ROWB + ((lane >> 3) & 1) * 16);

    float acc[4][4][4];
    #pragma unroll
    for (int i = 0; i < 4; i++)
        #pragma unroll
        for (int j = 0; j < 4; j++)
            #pragma unroll
            for (int q = 0; q < 4; q++) acc[i][j][q] = 0.f;

    issue_stage(rm0, v0, 0, sb);

    for (int kt = 0; kt < NSTG; kt++) {
        const uint32_t stb = sb + (kt & 1) * STAGE_B;
        if (kt + 1 < NSTG) {
            issue_stage(rm0, v0, (kt + 1) * BKg, sb + ((kt + 1) & 1) * STAGE_B);
            cp_wait<1>();
        } else {
            cp_wait<0>();
        }
        __syncthreads();

        #pragma unroll
        for (int ks = 0; ks < 2; ks++) {
            uint32_t bh[4][2];
            #pragma unroll
            for (int pr = 0; pr < 2; pr++) {
                uint32_t addr = stb + 2 * PLANE_B + bbase + pr * (16 * ROWB) + ks * 32;
                ldsm4(bh[pr * 2][0], bh[pr * 2][1], bh[pr * 2 + 1][0], bh[pr * 2 + 1][1], addr);
            }
            #pragma unroll
            for (int mt = 0; mt < 4; mt++) {
                uint32_t ah[4], alo[4];
                uint32_t addr = stb + abase + mt * (16 * ROWB) + ks * 32;
                ldsm4(ah[0], ah[1], ah[2], ah[3], addr);
                ldsm4(alo[0], alo[1], alo[2], alo[3], addr + PLANE_B);
                #pragma unroll
                for (int nt = 0; nt < 4; nt++) {
                    mma16816h(acc[mt][nt], ah,  bh[nt]);
                    mma16816h(acc[mt][nt], alo, bh[nt]);
                }
            }
        }
        __syncthreads();
    }

    const int r0 = rm0 + wm * 64 + (lane >> 2);
    const int c0 = v0 + wn * 32 + (lane & 3) * 2;
    #pragma unroll
    for (int nt = 0; nt < 4; nt++) {
        const int col = c0 + nt * 8;
        if (col < VV) {
            const float b0 = bias[col], b1 = bias[col + 1];
            #pragma unroll
            for (int mt = 0; mt < 4; mt++) {
                const int row = r0 + mt * 16;
                float* d = g_logits + (size_t)row * VV + col;
                float2 o0 = make_float2(acc[mt][nt][0] + b0, acc[mt][nt][1] + b1);
                float2 o1 = make_float2(acc[mt][nt][2] + b0, acc[mt][nt][3] + b1);
                *(float2*)d = o0;
                *(float2*)(d + 8 * VV) = o1;
            }
        }
    }
}

// ======================= 2) softmax + KL + ext log-prob gather =======================
__global__ __launch_bounds__(256)
void softmax_kl_kernel(const int* __restrict__ lens, const int* __restrict__ targets) {
    __shared__ float sh[16];
    const int t = blockIdx.x;
    const int p = blockIdx.y;
    const int tid = threadIdx.x;
    const int pb = p * TT + t;

    if (t >= lens[p]) {
        if (tid == 0) g_kl[pb] = 0.f;
        return;
    }
    const size_t r1 = (size_t)p * TT + t;
    const size_t r2 = (size_t)(p + NPAIR) * TT + t;
    const float* L1 = g_logits + r1 * VV;
    const float* L2 = g_logits + r2 * VV;
    const float4* L1v = (const float4*)L1;
    const float4* L2v = (const float4*)L2;

    float v1[2][4], v2[2][4];
    float m1 = -3.4e38f, m2 = -3.4e38f;
    #pragma unroll
    for (int q = 0; q < 2; q++) {
        int i = tid + q * 256;
        if (i < 500) {
            float4 a = L1v[i], b = L2v[i];
            v1[q][0] = a.x; v1[q][1] = a.y; v1[q][2] = a.z; v1[q][3] = a.w;
            v2[q][0] = b.x; v2[q][1] = b.y; v2[q][2] = b.z; v2[q][3] = b.w;
            #pragma unroll
            for (int k = 0; k < 4; k++) {
                m1 = fmaxf(m1, v1[q][k]);
                m2 = fmaxf(m2, v2[q][k]);
            }
        }
    }
    bmax2(m1, m2, sh);

    float e1[2][4], e2[2][4];
    float s1 = 0.f, s2 = 0.f;
    #pragma unroll
    for (int q = 0; q < 2; q++) {
        int i = tid + q * 256;
        if (i < 500) {
            #pragma unroll
            for (int k = 0; k < 4; k++) {
                e1[q][k] = __expf(v1[q][k] - m1); s1 += e1[q][k];
                e2[q][k] = __expf(v2[q][k] - m2); s2 += e2[q][k];
            }
        }
    }
    bsum2(s1, s2, sh);
    const float Z1 = s1, Z2 = s2;
    const float lZ1 = __logf(Z1), lZ2 = __logf(Z2);
    const float iZ1 = 1.f / Z1,   iZ2 = 1.f / Z2;

    float kl = 0.f;
    #pragma unroll
    for (int q = 0; q < 2; q++) {
        int i = tid + q * 256;
        if (i < 500) {
            #pragma unroll
            for (int k = 0; k < 4; k++) {
                float p1 = v1[q][k] - m1 - lZ1;
                float p2 = v2[q][k] - m2 - lZ2;
                kl += (p1 - p2) * (e1[q][k] * iZ1 - e2[q][k] * iZ2);
            }
        }
    }
    kl = bsum(kl, sh);
    if (tid == 0) g_kl[pb] = kl;

    if (tid < 1 + UU) {
        int c = (tid == 0) ? 0 : targets[p * UU + (tid - 1)];
        g_lp[r1 * EXT + tid] = L1[c] - m1 - lZ1;
        g_lp[r2 * EXT + tid] = L2[c] - m2 - lZ2;
    }
}

// ======================= 3) CTC forward (log domain, measured-best R4 design) =======================
__global__ __launch_bounds__(256, 1)
void ctc_kernel(const int* __restrict__ lens, const int* __restrict__ targets,
                const int* __restrict__ tlens) {
    const int b = blockIdx.x;
    const int tid = threadIdx.x;
    const int len = lens[b];
    const int* tg = targets + b * UU;

    const int s = tid;
    const bool isstate = (s < SS);
    const int u = (s - 1) >> 1;
    const int pidx = (s & 1) ? (1 + u) : 0;
    bool can_skip = false;
    if (isstate && (s & 1) && s >= 3) can_skip = (tg[u] != tg[u - 1]);

    __shared__ float al[2][SS + 3];
    __shared__ float lpb[2][16][EXT];

    const float* base = g_lp + (size_t)b * TT * EXT;
    const int nchunk = (len + 15) / 16;

    {
        int n0 = min(16, len) * EXT;
        for (int i = tid; i < n0; i += 256) (&lpb[0][0][0])[i] = base[i];
    }
    __syncthreads();

    if (isstate) {
        float v = NEGF;
        if (s == 0) v = lpb[0][0][0];
        if (s == 1) v = lpb[0][0][1];
        al[0][s] = v;
    }
    __syncthreads();

    int curbuf = 0;
    float stage[7];
    for (int c = 0; c < nchunk; c++) {
        int nn = 0;
        const int tn0 = (c + 1) * 16;
        if (c + 1 < nchunk) {
            nn = (min(tn0 + 16, len) - tn0) * EXT;
            #pragma unroll
            for (int q = 0; q < 7; q++) {
                int i = tid + q * 256;
                stage[q] = (i < nn) ? base[(size_t)tn0 * EXT + i] : 0.f;
            }
        }
        const int t0 = c * 16;
        const int te = min(t0 + 16, len);
        for (int t = max(t0, 1); t < te; t++) {
            if (isstate) {
                const float lp = lpb[c & 1][t - t0][pidx];
                const float a  = al[curbuf][s];
                const float bb = (s >= 1) ? al[curbuf][s - 1] : NEGF;
                const float cc = can_skip ? al[curbuf][s - 2] : NEGF;
                const float m = fmaxf(a, fmaxf(bb, cc));
                const float r = __expf(a - m) + __expf(bb - m) + __expf(cc - m);
                al[curbuf ^ 1][s] = m + __logf(r) + lp;
            }
            __syncthreads();
            curbuf ^= 1;
        }
        if (c + 1 < nchunk) {
            #pragma unroll
            for (int q = 0; q < 7; q++) {
                int i = tid + q * 256;
                if (i < nn) (&lpb[(c + 1) & 1][0][0])[i] = stage[q];
            }
        }
        __syncthreads();
    }

    if (tid == 0) {
        const int e = 2 * tlens[b];
        const float a = al[curbuf][e];
        const float bb = al[curbuf][e - 1];
        const float m = fmaxf(a, bb);
        g_ctc[b] = -(m + __logf(__expf(a - m) + __expf(bb - m)));
    }
}

// ======================= 4) final reduction =======================
__global__ __launch_bounds__(256)
void reduce_kernel(float* __restrict__ out) {
    __shared__ float sh[8];
    const int tid = threadIdx.x;
    float skl = 0.f;
    for (int i = tid; i < NPAIR * TT; i += 256) skl += g_kl[i];
    float sctc = (tid < NB) ? g_ctc[tid] : 0.f;
    skl = bsum(skl, sh);
    sctc = bsum(sctc, sh);
    if (tid == 0) {
        out[0] = 0.5f * sctc;
        out[1] = 0.5f * skl;
    }
}

extern "C" void kernel_launch(void* const* d_in, const int* in_sizes, int n_in,
                              void* d_out, int out_size) {
    const float* enc     = (const float*)d_in[0];
    const float* W       = (const float*)d_in[1];
    const float* bias    = (const float*)d_in[2];
    const int*   lens    = (const int*)d_in[3];
    const int*   targets = (const int*)d_in[4];
    const int*   tlens   = (const int*)d_in[5];
    float* out = (float*)d_out;

    cudaFuncSetAttribute(gemm_hmma_kernel, cudaFuncAttributeMaxDynamicSharedMemorySize, GEMM_SMEM);

    const int NA4 = NB * TT * CC / 4;
    const int NW4 = 2048 * CC / 4;
    convert_kernel<<<(NA4 + NW4 + 255) / 256, 256>>>(enc, W);

    dim3 gg((VV + BNg - 1) / BNg, (NB * TT) / BMg);
    gemm_hmma_kernel<<<gg, 256, GEMM_SMEM>>>(lens, bias);

    dim3 g2(TT, NPAIR);
    softmax_kl_kernel<<<g2, 256>>>(lens, targets);

    ctc_kernel<<<NB, 256>>>(lens, targets, tlens);

    reduce_kernel<<<1, 256>>>(out);
}

// round 11
// speedup vs baseline: 2.9434x; 1.3064x over previous
#include <cuda_runtime.h>
#include <cuda_fp16.h>
#include <math.h>
#include <stdint.h>

#define TT   1000
#define NB   32
#define NPAIR 16
#define VV   2000
#define CC   512
#define UU   100
#define SS   201
#define EXT  104
#define NEGF (-1.0e30f)

#define BMg 128
#define BNg 128
#define BKg 32
#define NSTG (CC / BKg)
#define ROWB 80
#define PLANE_B (BMg * ROWB)      // 10240
#define STAGE_B (2 * PLANE_B)     // Ah, Wh
#define GEMM_SMEM (2 * STAGE_B)   // 40960

__device__ float g_logits[(size_t)NB * TT * VV];
__device__ float g_lp[(size_t)NB * TT * EXT];   // natural-log probs at ext classes
__device__ float g_kl[NPAIR * TT];
__device__ float g_ctc[NB];
__device__ __half g_Ah[(size_t)NB * TT * CC];
__device__ __half g_Wh[(size_t)2048 * CC];      // vocab padded to 2048 rows

__device__ __forceinline__ uint32_t s2u(const void* p) {
    uint32_t a;
    asm("{ .reg .u64 t; cvta.to.shared.u64 t, %1; cvt.u32.u64 %0, t; }" : "=r"(a) : "l"(p));
    return a;
}
__device__ __forceinline__ void cp_async16(uint32_t dst, const void* src) {
    asm volatile("cp.async.cg.shared.global [%0], [%1], 16;" :: "r"(dst), "l"(src) : "memory");
}
__device__ __forceinline__ void cp_commit() {
    asm volatile("cp.async.commit_group;" ::: "memory");
}
template <int N>
__device__ __forceinline__ void cp_wait() {
    asm volatile("cp.async.wait_group %0;" :: "n"(N) : "memory");
}
__device__ __forceinline__ void ldsm4(uint32_t& r0, uint32_t& r1, uint32_t& r2, uint32_t& r3,
                                      uint32_t a) {
    asm volatile("ldmatrix.sync.aligned.m8n8.x4.shared.b16 {%0,%1,%2,%3}, [%4];"
                 : "=r"(r0), "=r"(r1), "=r"(r2), "=r"(r3) : "r"(a));
}
__device__ __forceinline__ void mma16816h(float* c, const uint32_t* a, const uint32_t* b) {
    asm volatile(
        "mma.sync.aligned.m16n8k16.row.col.f32.f16.f16.f32 "
        "{%0,%1,%2,%3}, {%4,%5,%6,%7}, {%8,%9}, {%0,%1,%2,%3};"
        : "+f"(c[0]), "+f"(c[1]), "+f"(c[2]), "+f"(c[3])
        : "r"(a[0]), "r"(a[1]), "r"(a[2]), "r"(a[3]), "r"(b[0]), "r"(b[1]));
}

// ---- block reductions (single and paired) ----
__device__ __forceinline__ float bsum(float v, float* sh) {
    #pragma unroll
    for (int o = 16; o; o >>= 1) v += __shfl_xor_sync(0xffffffffu, v, o);
    __syncthreads();
    if ((threadIdx.x & 31) == 0) sh[threadIdx.x >> 5] = v;
    __syncthreads();
    if (threadIdx.x == 0) {
        float t = 0.f;
        #pragma unroll
        for (int i = 0; i < 8; i++) t += sh[i];
        sh[0] = t;
    }
    __syncthreads();
    return sh[0];
}
__device__ __forceinline__ void bmax2(float& x, float& y, float* sh) {
    #pragma unroll
    for (int o = 16; o; o >>= 1) {
        x = fmaxf(x, __shfl_xor_sync(0xffffffffu, x, o));
        y = fmaxf(y, __shfl_xor_sync(0xffffffffu, y, o));
    }
    __syncthreads();
    if ((threadIdx.x & 31) == 0) {
        sh[(threadIdx.x >> 5) * 2]     = x;
        sh[(threadIdx.x >> 5) * 2 + 1] = y;
    }
    __syncthreads();
    if (threadIdx.x == 0) {
        float tx = sh[0], ty = sh[1];
        #pragma unroll
        for (int i = 1; i < 8; i++) {
            tx = fmaxf(tx, sh[i * 2]);
            ty = fmaxf(ty, sh[i * 2 + 1]);
        }
        sh[0] = tx; sh[1] = ty;
    }
    __syncthreads();
    x = sh[0]; y = sh[1];
}
__device__ __forceinline__ void bsum2(float& x, float& y, float* sh) {
    #pragma unroll
    for (int o = 16; o; o >>= 1) {
        x += __shfl_xor_sync(0xffffffffu, x, o);
        y += __shfl_xor_sync(0xffffffffu, y, o);
    }
    __syncthreads();
    if ((threadIdx.x & 31) == 0) {
        sh[(threadIdx.x >> 5) * 2]     = x;
        sh[(threadIdx.x >> 5) * 2 + 1] = y;
    }
    __syncthreads();
    if (threadIdx.x == 0) {
        float tx = 0.f, ty = 0.f;
        #pragma unroll
        for (int i = 0; i < 8; i++) {
            tx += sh[i * 2];
            ty += sh[i * 2 + 1];
        }
        sh[0] = tx; sh[1] = ty;
    }
    __syncthreads();
    x = sh[0]; y = sh[1];
}

// ======================= 0) fp32 -> fp16 round (A and W) =======================
__global__ __launch_bounds__(256)
void convert_kernel(const float* __restrict__ enc, const float* __restrict__ W) {
    const int NA4 = NB * TT * CC / 4;
    const int NW4 = 2048 * CC / 4;
    int i = blockIdx.x * 256 + threadIdx.x;
    if (i < NA4) {
        float4 v = ((const float4*)enc)[i];
        float a[4] = {v.x, v.y, v.z, v.w};
        union { __half h[4]; uint2 u; } H;
        #pragma unroll
        for (int k = 0; k < 4; k++) H.h[k] = __float2half_rn(a[k]);
        *(uint2*)(g_Ah + (size_t)i * 4) = H.u;
    } else if (i < NA4 + NW4) {
        int j = i - NA4;
        int row = j >> 7;
        float4 v = (row < VV) ? ((const float4*)W)[j] : make_float4(0.f, 0.f, 0.f, 0.f);
        float a[4] = {v.x, v.y, v.z, v.w};
        union { __half h[4]; uint2 u; } H;
        #pragma unroll
        for (int k = 0; k < 4; k++) H.h[k] = __float2half_rn(a[k]);
        *(uint2*)(g_Wh + (size_t)j * 4) = H.u;
    }
}

// ======================= 1) HMMA GEMM (single fp16 product) =======================
__device__ __forceinline__ void issue_stage(int rm0, int v0, int k0, uint32_t stb) {
    const int tid = threadIdx.x;
    #pragma unroll
    for (int j = 0; j < 4; j++) {
        const int g = tid + j * 256;          // 0..1023
        const int plane = g >> 9;             // 0:Ah 1:Wh
        const int idx = g & 511;
        const int row = idx >> 2;
        const int cch = idx & 3;
        const __half* sp;
        int grow;
        if (plane == 0) { sp = g_Ah; grow = rm0 + row; }
        else            { sp = g_Wh; grow = v0 + row; }
        uint32_t dst = stb + plane * PLANE_B + row * ROWB + cch * 16;
        cp_async16(dst, sp + (size_t)grow * CC + k0 + cch * 8);
    }
    cp_commit();
}

__global__ __launch_bounds__(256, 2)
void gemm_hmma_kernel(const int* __restrict__ lens, const float* __restrict__ bias) {
    const int v0  = blockIdx.x * BNg;
    const int rm0 = blockIdx.y * BMg;
    {
        int b_first = rm0 / TT, b_last = (rm0 + BMg - 1) / TT;
        bool act = false;
        for (int b = b_first; b <= b_last && b < NB; b++) {
            int t_lo = max(rm0, b * TT) - b * TT;
            if (t_lo < lens[b]) act = true;
        }
        if (!act) return;
    }
    extern __shared__ char smem[];
    const uint32_t sb = s2u(smem);
    const int tid = threadIdx.x;
    const int lane = tid & 31;
    const int wid = tid >> 5;
    const int wm = wid >> 2;
    const int wn = wid & 3;

    const uint32_t abase = (uint32_t)((wm * 64 + (lane & 15)) * ROWB + (lane >> 4) * 16);
    const int n_l = (lane & 7) + ((lane >> 4) << 3);
    const uint32_t bbase = (uint32_t)((wn * 32 + n_l) * ROWB + ((lane >> 3) & 1) * 16);

    float acc[4][4][4];
    #pragma unroll
    for (int i = 0; i < 4; i++)
        #pragma unroll
        for (int j = 0; j < 4; j++)
            #pragma unroll
            for (int q = 0; q < 4; q++) acc[i][j][q] = 0.f;

    issue_stage(rm0, v0, 0, sb);

    for (int kt = 0; kt < NSTG; kt++) {
        const uint32_t stb = sb + (kt & 1) * STAGE_B;
        if (kt + 1 < NSTG) {
            issue_stage(rm0, v0, (kt + 1) * BKg, sb + ((kt + 1) & 1) * STAGE_B);
            cp_wait<1>();
        } else {
            cp_wait<0>();
        }
        __syncthreads();

        #pragma unroll
        for (int ks = 0; ks < 2; ks++) {
            uint32_t bh[4][2];
            #pragma unroll
            for (int pr = 0; pr < 2; pr++) {
                uint32_t addr = stb + PLANE_B + bbase + pr * (16 * ROWB) + ks * 32;
                ldsm4(bh[pr * 2][0], bh[pr * 2][1], bh[pr * 2 + 1][0], bh[pr * 2 + 1][1], addr);
            }
            #pragma unroll
            for (int mt = 0; mt < 4; mt++) {
                uint32_t ah[4];
                uint32_t addr = stb + abase + mt * (16 * ROWB) + ks * 32;
                ldsm4(ah[0], ah[1], ah[2], ah[3], addr);
                #pragma unroll
                for (int nt = 0; nt < 4; nt++) {
                    mma16816h(acc[mt][nt], ah, bh[nt]);
                }
            }
        }
        __syncthreads();
    }

    const int r0 = rm0 + wm * 64 + (lane >> 2);
    const int c0 = v0 + wn * 32 + (lane & 3) * 2;
    #pragma unroll
    for (int nt = 0; nt < 4; nt++) {
        const int col = c0 + nt * 8;
        if (col < VV) {
            const float b0 = bias[col], b1 = bias[col + 1];
            #pragma unroll
            for (int mt = 0; mt < 4; mt++) {
                const int row = r0 + mt * 16;
                float* d = g_logits + (size_t)row * VV + col;
                float2 o0 = make_float2(acc[mt][nt][0] + b0, acc[mt][nt][1] + b1);
                float2 o1 = make_float2(acc[mt][nt][2] + b0, acc[mt][nt][3] + b1);
                *(float2*)d = o0;
                *(float2*)(d + 8 * VV) = o1;
            }
        }
    }
}

// ======================= 2) softmax + KL + ext log-prob gather =======================
__global__ __launch_bounds__(256)
void softmax_kl_kernel(const int* __restrict__ lens, const int* __restrict__ targets) {
    __shared__ float sh[16];
    const int t = blockIdx.x;
    const int p = blockIdx.y;
    const int tid = threadIdx.x;
    const int pb = p * TT + t;

    if (t >= lens[p]) {
        if (tid == 0) g_kl[pb] = 0.f;
        return;
    }
    const size_t r1 = (size_t)p * TT + t;
    const size_t r2 = (size_t)(p + NPAIR) * TT + t;
    const float* L1 = g_logits + r1 * VV;
    const float* L2 = g_logits + r2 * VV;
    const float4* L1v = (const float4*)L1;
    const float4* L2v = (const float4*)L2;

    float v1[2][4], v2[2][4];
    float m1 = -3.4e38f, m2 = -3.4e38f;
    #pragma unroll
    for (int q = 0; q < 2; q++) {
        int i = tid + q * 256;
        if (i < 500) {
            float4 a = L1v[i], b = L2v[i];
            v1[q][0] = a.x; v1[q][1] = a.y; v1[q][2] = a.z; v1[q][3] = a.w;
            v2[q][0] = b.x; v2[q][1] = b.y; v2[q][2] = b.z; v2[q][3] = b.w;
            #pragma unroll
            for (int k = 0; k < 4; k++) {
                m1 = fmaxf(m1, v1[q][k]);
                m2 = fmaxf(m2, v2[q][k]);
            }
        }
    }
    bmax2(m1, m2, sh);

    float e1[2][4], e2[2][4];
    float s1 = 0.f, s2 = 0.f;
    #pragma unroll
    for (int q = 0; q < 2; q++) {
        int i = tid + q * 256;
        if (i < 500) {
            #pragma unroll
            for (int k = 0; k < 4; k++) {
                e1[q][k] = __expf(v1[q][k] - m1); s1 += e1[q][k];
                e2[q][k] = __expf(v2[q][k] - m2); s2 += e2[q][k];
            }
        }
    }
    bsum2(s1, s2, sh);
    const float Z1 = s1, Z2 = s2;
    const float lZ1 = __logf(Z1), lZ2 = __logf(Z2);
    const float iZ1 = 1.f / Z1,   iZ2 = 1.f / Z2;

    float kl = 0.f;
    #pragma unroll
    for (int q = 0; q < 2; q++) {
        int i = tid + q * 256;
        if (i < 500) {
            #pragma unroll
            for (int k = 0; k < 4; k++) {
                float p1 = v1[q][k] - m1 - lZ1;
                float p2 = v2[q][k] - m2 - lZ2;
                kl += (p1 - p2) * (e1[q][k] * iZ1 - e2[q][k] * iZ2);
            }
        }
    }
    kl = bsum(kl, sh);
    if (tid == 0) g_kl[pb] = kl;

    if (tid < 1 + UU) {
        int c = (tid == 0) ? 0 : targets[p * UU + (tid - 1)];
        g_lp[r1 * EXT + tid] = L1[c] - m1 - lZ1;
        g_lp[r2 * EXT + tid] = L2[c] - m2 - lZ2;
    }
}

// ======================= 3) CTC forward (log domain, measured-best R4 design) =======================
__global__ __launch_bounds__(256, 1)
void ctc_kernel(const int* __restrict__ lens, const int* __restrict__ targets,
                const int* __restrict__ tlens) {
    const int b = blockIdx.x;
    const int tid = threadIdx.x;
    const int len = lens[b];
    const int* tg = targets + b * UU;

    const int s = tid;
    const bool isstate = (s < SS);
    const int u = (s - 1) >> 1;
    const int pidx = (s & 1) ? (1 + u) : 0;
    bool can_skip = false;
    if (isstate && (s & 1) && s >= 3) can_skip = (tg[u] != tg[u - 1]);

    __shared__ float al[2][SS + 3];
    __shared__ float lpb[2][16][EXT];

    const float* base = g_lp + (size_t)b * TT * EXT;
    const int nchunk = (len + 15) / 16;

    {
        int n0 = min(16, len) * EXT;
        for (int i = tid; i < n0; i += 256) (&lpb[0][0][0])[i] = base[i];
    }
    __syncthreads();

    if (isstate) {
        float v = NEGF;
        if (s == 0) v = lpb[0][0][0];
        if (s == 1) v = lpb[0][0][1];
        al[0][s] = v;
    }
    __syncthreads();

    int curbuf = 0;
    float stage[7];
    for (int c = 0; c < nchunk; c++) {
        int nn = 0;
        const int tn0 = (c + 1) * 16;
        if (c + 1 < nchunk) {
            nn = (min(tn0 + 16, len) - tn0) * EXT;
            #pragma unroll
            for (int q = 0; q < 7; q++) {
                int i = tid + q * 256;
                stage[q] = (i < nn) ? base[(size_t)tn0 * EXT + i] : 0.f;
            }
        }
        const int t0 = c * 16;
        const int te = min(t0 + 16, len);
        for (int t = max(t0, 1); t < te; t++) {
            if (isstate) {
                const float lp = lpb[c & 1][t - t0][pidx];
                const float a  = al[curbuf][s];
                const float bb = (s >= 1) ? al[curbuf][s - 1] : NEGF;
                const float cc = can_skip ? al[curbuf][s - 2] : NEGF;
                const float m = fmaxf(a, fmaxf(bb, cc));
                const float r = __expf(a - m) + __expf(bb - m) + __expf(cc - m);
                al[curbuf ^ 1][s] = m + __logf(r) + lp;
            }
            __syncthreads();
            curbuf ^= 1;
        }
        if (c + 1 < nchunk) {
            #pragma unroll
            for (int q = 0; q < 7; q++) {
                int i = tid + q * 256;
                if (i < nn) (&lpb[(c + 1) & 1][0][0])[i] = stage[q];
            }
        }
        __syncthreads();
    }

    if (tid == 0) {
        const int e = 2 * tlens[b];
        const float a = al[curbuf][e];
        const float bb = al[curbuf][e - 1];
        const float m = fmaxf(a, bb);
        g_ctc[b] = -(m + __logf(__expf(a - m) + __expf(bb - m)));
    }
}

// ======================= 4) final reduction =======================
__global__ __launch_bounds__(256)
void reduce_kernel(float* __restrict__ out) {
    __shared__ float sh[8];
    const int tid = threadIdx.x;
    float skl = 0.f;
    for (int i = tid; i < NPAIR * TT; i += 256) skl += g_kl[i];
    float sctc = (tid < NB) ? g_ctc[tid] : 0.f;
    skl = bsum(skl, sh);
    sctc = bsum(sctc, sh);
    if (tid == 0) {
        out[0] = 0.5f * sctc;
        out[1] = 0.5f * skl;
    }
}

extern "C" void kernel_launch(void* const* d_in, const int* in_sizes, int n_in,
                              void* d_out, int out_size) {
    const float* enc     = (const float*)d_in[0];
    const float* W       = (const float*)d_in[1];
    const float* bias    = (const float*)d_in[2];
    const int*   lens    = (const int*)d_in[3];
    const int*   targets = (const int*)d_in[4];
    const int*   tlens   = (const int*)d_in[5];
    float* out = (float*)d_out;

    cudaFuncSetAttribute(gemm_hmma_kernel, cudaFuncAttributeMaxDynamicSharedMemorySize, GEMM_SMEM);

    const int NA4 = NB * TT * CC / 4;
    const int NW4 = 2048 * CC / 4;
    convert_kernel<<<(NA4 + NW4 + 255) / 256, 256>>>(enc, W);

    dim3 gg((VV + BNg - 1) / BNg, (NB * TT) / BMg);
    gemm_hmma_kernel<<<gg, 256, GEMM_SMEM>>>(lens, bias);

    dim3 g2(TT, NPAIR);
    softmax_kl_kernel<<<g2, 256>>>(lens, targets);

    ctc_kernel<<<NB, 256>>>(lens, targets, tlens);

    reduce_kernel<<<1, 256>>>(out);
}

// round 12
// speedup vs baseline: 2.9504x; 1.0024x over previous
#include <cuda_runtime.h>
#include <cuda_fp16.h>
#include <math.h>
#include <stdint.h>

#define TT   1000
#define NB   32
#define NPAIR 16
#define VV   2000
#define CC   512
#define UU   100
#define SS   201
#define EXT  104
#define NEGF (-1.0e30f)

#define BMg 128
#define BNg 128
#define BKg 32
#define NSTG (CC / BKg)
#define ROWB 80
#define PLANE_B (BMg * ROWB)      // 10240
#define STAGE_B (2 * PLANE_B)     // Ah, Wh
#define GEMM_SMEM (2 * STAGE_B)   // 40960

__device__ __half g_logits[(size_t)NB * TT * VV];   // fp16 logits (128 MB)
__device__ float g_lp[(size_t)NB * TT * EXT];       // natural-log probs at ext classes
__device__ float g_kl[NPAIR * TT];
__device__ float g_ctc[NB];
__device__ __half g_Ah[(size_t)NB * TT * CC];
__device__ __half g_Wh[(size_t)2048 * CC];          // vocab padded to 2048 rows

__device__ __forceinline__ uint32_t s2u(const void* p) {
    uint32_t a;
    asm("{ .reg .u64 t; cvta.to.shared.u64 t, %1; cvt.u32.u64 %0, t; }" : "=r"(a) : "l"(p));
    return a;
}
__device__ __forceinline__ void cp_async16(uint32_t dst, const void* src) {
    asm volatile("cp.async.cg.shared.global [%0], [%1], 16;" :: "r"(dst), "l"(src) : "memory");
}
__device__ __forceinline__ void cp_commit() {
    asm volatile("cp.async.commit_group;" ::: "memory");
}
template <int N>
__device__ __forceinline__ void cp_wait() {
    asm volatile("cp.async.wait_group %0;" :: "n"(N) : "memory");
}
__device__ __forceinline__ void ldsm4(uint32_t& r0, uint32_t& r1, uint32_t& r2, uint32_t& r3,
                                      uint32_t a) {
    asm volatile("ldmatrix.sync.aligned.m8n8.x4.shared.b16 {%0,%1,%2,%3}, [%4];"
                 : "=r"(r0), "=r"(r1), "=r"(r2), "=r"(r3) : "r"(a));
}
__device__ __forceinline__ void mma16816h(float* c, const uint32_t* a, const uint32_t* b) {
    asm volatile(
        "mma.sync.aligned.m16n8k16.row.col.f32.f16.f16.f32 "
        "{%0,%1,%2,%3}, {%4,%5,%6,%7}, {%8,%9}, {%0,%1,%2,%3};"
        : "+f"(c[0]), "+f"(c[1]), "+f"(c[2]), "+f"(c[3])
        : "r"(a[0]), "r"(a[1]), "r"(a[2]), "r"(a[3]), "r"(b[0]), "r"(b[1]));
}

// ---- block reductions (single and paired) ----
__device__ __forceinline__ float bsum(float v, float* sh) {
    #pragma unroll
    for (int o = 16; o; o >>= 1) v += __shfl_xor_sync(0xffffffffu, v, o);
    __syncthreads();
    if ((threadIdx.x & 31) == 0) sh[threadIdx.x >> 5] = v;
    __syncthreads();
    if (threadIdx.x == 0) {
        float t = 0.f;
        #pragma unroll
        for (int i = 0; i < 8; i++) t += sh[i];
        sh[0] = t;
    }
    __syncthreads();
    return sh[0];
}
__device__ __forceinline__ void bmax2(float& x, float& y, float* sh) {
    #pragma unroll
    for (int o = 16; o; o >>= 1) {
        x = fmaxf(x, __shfl_xor_sync(0xffffffffu, x, o));
        y = fmaxf(y, __shfl_xor_sync(0xffffffffu, y, o));
    }
    __syncthreads();
    if ((threadIdx.x & 31) == 0) {
        sh[(threadIdx.x >> 5) * 2]     = x;
        sh[(threadIdx.x >> 5) * 2 + 1] = y;
    }
    __syncthreads();
    if (threadIdx.x == 0) {
        float tx = sh[0], ty = sh[1];
        #pragma unroll
        for (int i = 1; i < 8; i++) {
            tx = fmaxf(tx, sh[i * 2]);
            ty = fmaxf(ty, sh[i * 2 + 1]);
        }
        sh[0] = tx; sh[1] = ty;
    }
    __syncthreads();
    x = sh[0]; y = sh[1];
}
__device__ __forceinline__ void bsum2(float& x, float& y, float* sh) {
    #pragma unroll
    for (int o = 16; o; o >>= 1) {
        x += __shfl_xor_sync(0xffffffffu, x, o);
        y += __shfl_xor_sync(0xffffffffu, y, o);
    }
    __syncthreads();
    if ((threadIdx.x & 31) == 0) {
        sh[(threadIdx.x >> 5) * 2]     = x;
        sh[(threadIdx.x >> 5) * 2 + 1] = y;
    }
    __syncthreads();
    if (threadIdx.x == 0) {
        float tx = 0.f, ty = 0.f;
        #pragma unroll
        for (int i = 0; i < 8; i++) {
            tx += sh[i * 2];
            ty += sh[i * 2 + 1];
        }
        sh[0] = tx; sh[1] = ty;
    }
    __syncthreads();
    x = sh[0]; y = sh[1];
}

// ======================= 0) fp32 -> fp16 round (A and W) =======================
__global__ __launch_bounds__(256)
void convert_kernel(const float* __restrict__ enc, const float* __restrict__ W) {
    const int NA4 = NB * TT * CC / 4;
    const int NW4 = 2048 * CC / 4;
    int i = blockIdx.x * 256 + threadIdx.x;
    if (i < NA4) {
        float4 v = ((const float4*)enc)[i];
        float a[4] = {v.x, v.y, v.z, v.w};
        union { __half h[4]; uint2 u; } H;
        #pragma unroll
        for (int k = 0; k < 4; k++) H.h[k] = __float2half_rn(a[k]);
        *(uint2*)(g_Ah + (size_t)i * 4) = H.u;
    } else if (i < NA4 + NW4) {
        int j = i - NA4;
        int row = j >> 7;
        float4 v = (row < VV) ? ((const float4*)W)[j] : make_float4(0.f, 0.f, 0.f, 0.f);
        float a[4] = {v.x, v.y, v.z, v.w};
        union { __half h[4]; uint2 u; } H;
        #pragma unroll
        for (int k = 0; k < 4; k++) H.h[k] = __float2half_rn(a[k]);
        *(uint2*)(g_Wh + (size_t)j * 4) = H.u;
    }
}

// ======================= 1) HMMA GEMM (single fp16 product, fp16 logits out) =======================
__device__ __forceinline__ void issue_stage(int rm0, int v0, int k0, uint32_t stb) {
    const int tid = threadIdx.x;
    #pragma unroll
    for (int j = 0; j < 4; j++) {
        const int g = tid + j * 256;          // 0..1023
        const int plane = g >> 9;             // 0:Ah 1:Wh
        const int idx = g & 511;
        const int row = idx >> 2;
        const int cch = idx & 3;
        const __half* sp;
        int grow;
        if (plane == 0) { sp = g_Ah; grow = rm0 + row; }
        else            { sp = g_Wh; grow = v0 + row; }
        uint32_t dst = stb + plane * PLANE_B + row * ROWB + cch * 16;
        cp_async16(dst, sp + (size_t)grow * CC + k0 + cch * 8);
    }
    cp_commit();
}

__global__ __launch_bounds__(256, 2)
void gemm_hmma_kernel(const int* __restrict__ lens, const float* __restrict__ bias) {
    const int v0  = blockIdx.x * BNg;
    const int rm0 = blockIdx.y * BMg;
    {
        int b_first = rm0 / TT, b_last = (rm0 + BMg - 1) / TT;
        bool act = false;
        for (int b = b_first; b <= b_last && b < NB; b++) {
            int t_lo = max(rm0, b * TT) - b * TT;
            if (t_lo < lens[b]) act = true;
        }
        if (!act) return;
    }
    extern __shared__ char smem[];
    const uint32_t sb = s2u(smem);
    const int tid = threadIdx.x;
    const int lane = tid & 31;
    const int wid = tid >> 5;
    const int wm = wid >> 2;
    const int wn = wid & 3;

    const uint32_t abase = (uint32_t)((wm * 64 + (lane & 15)) * ROWB + (lane >> 4) * 16);
    const int n_l = (lane & 7) + ((lane >> 4) << 3);
    const uint32_t bbase = (uint32_t)((wn * 32 + n_l) * ROWB + ((lane >> 3) & 1) * 16);

    float acc[4][4][4];
    #pragma unroll
    for (int i = 0; i < 4; i++)
        #pragma unroll
        for (int j = 0; j < 4; j++)
            #pragma unroll
            for (int q = 0; q < 4; q++) acc[i][j][q] = 0.f;

    issue_stage(rm0, v0, 0, sb);

    for (int kt = 0; kt < NSTG; kt++) {
        const uint32_t stb = sb + (kt & 1) * STAGE_B;
        if (kt + 1 < NSTG) {
            issue_stage(rm0, v0, (kt + 1) * BKg, sb + ((kt + 1) & 1) * STAGE_B);
            cp_wait<1>();
        } else {
            cp_wait<0>();
        }
        __syncthreads();

        #pragma unroll
        for (int ks = 0; ks < 2; ks++) {
            uint32_t bh[4][2];
            #pragma unroll
            for (int pr = 0; pr < 2; pr++) {
                uint32_t addr = stb + PLANE_B + bbase + pr * (16 * ROWB) + ks * 32;
                ldsm4(bh[pr * 2][0], bh[pr * 2][1], bh[pr * 2 + 1][0], bh[pr * 2 + 1][1], addr);
            }
            #pragma unroll
            for (int mt = 0; mt < 4; mt++) {
                uint32_t ah[4];
                uint32_t addr = stb + abase + mt * (16 * ROWB) + ks * 32;
                ldsm4(ah[0], ah[1], ah[2], ah[3], addr);
                #pragma unroll
                for (int nt = 0; nt < 4; nt++) {
                    mma16816h(acc[mt][nt], ah, bh[nt]);
                }
            }
        }
        __syncthreads();
    }

    const int r0 = rm0 + wm * 64 + (lane >> 2);
    const int c0 = v0 + wn * 32 + (lane & 3) * 2;
    #pragma unroll
    for (int nt = 0; nt < 4; nt++) {
        const int col = c0 + nt * 8;
        if (col < VV) {
            const float b0 = bias[col], b1 = bias[col + 1];
            #pragma unroll
            for (int mt = 0; mt < 4; mt++) {
                const int row = r0 + mt * 16;
                __half* d = g_logits + (size_t)row * VV + col;
                *(__half2*)d = __floats2half2_rn(acc[mt][nt][0] + b0, acc[mt][nt][1] + b1);
                *(__half2*)(d + 8 * VV) = __floats2half2_rn(acc[mt][nt][2] + b0, acc[mt][nt][3] + b1);
            }
        }
    }
}

// ======================= 2) softmax + KL + ext log-prob gather (fp16 logits in) ==========
__global__ __launch_bounds__(256)
void softmax_kl_kernel(const int* __restrict__ lens, const int* __restrict__ targets) {
    __shared__ float sh[16];
    const int t = blockIdx.x;
    const int p = blockIdx.y;
    const int tid = threadIdx.x;
    const int pb = p * TT + t;

    if (t >= lens[p]) {
        if (tid == 0) g_kl[pb] = 0.f;
        return;
    }
    const size_t r1 = (size_t)p * TT + t;
    const size_t r2 = (size_t)(p + NPAIR) * TT + t;
    const __half* L1 = g_logits + r1 * VV;
    const __half* L2 = g_logits + r2 * VV;
    const uint4* L1v = (const uint4*)L1;     // 8 halves per uint4; 250 loads cover 2000
    const uint4* L2v = (const uint4*)L2;

    float v1[8], v2[8];
    float m1 = -3.4e38f, m2 = -3.4e38f;
    const bool act = (tid < 250);
    if (act) {
        union { uint4 u; __half2 h[4]; } U1, U2;
        U1.u = L1v[tid];
        U2.u = L2v[tid];
        #pragma unroll
        for (int k = 0; k < 4; k++) {
            float2 f1 = __half22float2(U1.h[k]);
            float2 f2 = __half22float2(U2.h[k]);
            v1[k * 2] = f1.x; v1[k * 2 + 1] = f1.y;
            v2[k * 2] = f2.x; v2[k * 2 + 1] = f2.y;
        }
        #pragma unroll
        for (int k = 0; k < 8; k++) {
            m1 = fmaxf(m1, v1[k]);
            m2 = fmaxf(m2, v2[k]);
        }
    }
    bmax2(m1, m2, sh);

    float e1[8], e2[8];
    float s1 = 0.f, s2 = 0.f;
    if (act) {
        #pragma unroll
        for (int k = 0; k < 8; k++) {
            e1[k] = __expf(v1[k] - m1); s1 += e1[k];
            e2[k] = __expf(v2[k] - m2); s2 += e2[k];
        }
    }
    bsum2(s1, s2, sh);
    const float Z1 = s1, Z2 = s2;
    const float lZ1 = __logf(Z1), lZ2 = __logf(Z2);
    const float iZ1 = 1.f / Z1,   iZ2 = 1.f / Z2;

    float kl = 0.f;
    if (act) {
        #pragma unroll
        for (int k = 0; k < 8; k++) {
            float p1 = v1[k] - m1 - lZ1;
            float p2 = v2[k] - m2 - lZ2;
            kl += (p1 - p2) * (e1[k] * iZ1 - e2[k] * iZ2);
        }
    }
    kl = bsum(kl, sh);
    if (tid == 0) g_kl[pb] = kl;

    if (tid < 1 + UU) {
        int c = (tid == 0) ? 0 : targets[p * UU + (tid - 1)];
        g_lp[r1 * EXT + tid] = __half2float(L1[c]) - m1 - lZ1;
        g_lp[r2 * EXT + tid] = __half2float(L2[c]) - m2 - lZ2;
    }
}

// ======================= 3) CTC forward (log domain, measured-best R4 design) =======================
__global__ __launch_bounds__(256, 1)
void ctc_kernel(const int* __restrict__ lens, const int* __restrict__ targets,
                const int* __restrict__ tlens) {
    const int b = blockIdx.x;
    const int tid = threadIdx.x;
    const int len = lens[b];
    const int* tg = targets + b * UU;

    const int s = tid;
    const bool isstate = (s < SS);
    const int u = (s - 1) >> 1;
    const int pidx = (s & 1) ? (1 + u) : 0;
    bool can_skip = false;
    if (isstate && (s & 1) && s >= 3) can_skip = (tg[u] != tg[u - 1]);

    __shared__ float al[2][SS + 3];
    __shared__ float lpb[2][16][EXT];

    const float* base = g_lp + (size_t)b * TT * EXT;
    const int nchunk = (len + 15) / 16;

    {
        int n0 = min(16, len) * EXT;
        for (int i = tid; i < n0; i += 256) (&lpb[0][0][0])[i] = base[i];
    }
    __syncthreads();

    if (isstate) {
        float v = NEGF;
        if (s == 0) v = lpb[0][0][0];
        if (s == 1) v = lpb[0][0][1];
        al[0][s] = v;
    }
    __syncthreads();

    int curbuf = 0;
    float stage[7];
    for (int c = 0; c < nchunk; c++) {
        int nn = 0;
        const int tn0 = (c + 1) * 16;
        if (c + 1 < nchunk) {
            nn = (min(tn0 + 16, len) - tn0) * EXT;
            #pragma unroll
            for (int q = 0; q < 7; q++) {
                int i = tid + q * 256;
                stage[q] = (i < nn) ? base[(size_t)tn0 * EXT + i] : 0.f;
            }
        }
        const int t0 = c * 16;
        const int te = min(t0 + 16, len);
        for (int t = max(t0, 1); t < te; t++) {
            if (isstate) {
                const float lp = lpb[c & 1][t - t0][pidx];
                const float a  = al[curbuf][s];
                const float bb = (s >= 1) ? al[curbuf][s - 1] : NEGF;
                const float cc = can_skip ? al[curbuf][s - 2] : NEGF;
                const float m = fmaxf(a, fmaxf(bb, cc));
                const float r = __expf(a - m) + __expf(bb - m) + __expf(cc - m);
                al[curbuf ^ 1][s] = m + __logf(r) + lp;
            }
            __syncthreads();
            curbuf ^= 1;
        }
        if (c + 1 < nchunk) {
            #pragma unroll
            for (int q = 0; q < 7; q++) {
                int i = tid + q * 256;
                if (i < nn) (&lpb[(c + 1) & 1][0][0])[i] = stage[q];
            }
        }
        __syncthreads();
    }

    if (tid == 0) {
        const int e = 2 * tlens[b];
        const float a = al[curbuf][e];
        const float bb = al[curbuf][e - 1];
        const float m = fmaxf(a, bb);
        g_ctc[b] = -(m + __logf(__expf(a - m) + __expf(bb - m)));
    }
}

// ======================= 4) final reduction =======================
__global__ __launch_bounds__(256)
void reduce_kernel(float* __restrict__ out) {
    __shared__ float sh[8];
    const int tid = threadIdx.x;
    float skl = 0.f;
    for (int i = tid; i < NPAIR * TT; i += 256) skl += g_kl[i];
    float sctc = (tid < NB) ? g_ctc[tid] : 0.f;
    skl = bsum(skl, sh);
    sctc = bsum(sctc, sh);
    if (tid == 0) {
        out[0] = 0.5f * sctc;
        out[1] = 0.5f * skl;
    }
}

extern "C" void kernel_launch(void* const* d_in, const int* in_sizes, int n_in,
                              void* d_out, int out_size) {
    const float* enc     = (const float*)d_in[0];
    const float* W       = (const float*)d_in[1];
    const float* bias    = (const float*)d_in[2];
    const int*   lens    = (const int*)d_in[3];
    const int*   targets = (const int*)d_in[4];
    const int*   tlens   = (const int*)d_in[5];
    float* out = (float*)d_out;

    cudaFuncSetAttribute(gemm_hmma_kernel, cudaFuncAttributeMaxDynamicSharedMemorySize, GEMM_SMEM);

    const int NA4 = NB * TT * CC / 4;
    const int NW4 = 2048 * CC / 4;
    convert_kernel<<<(NA4 + NW4 + 255) / 256, 256>>>(enc, W);

    dim3 gg((VV + BNg - 1) / BNg, (NB * TT) / BMg);
    gemm_hmma_kernel<<<gg, 256, GEMM_SMEM>>>(lens, bias);

    dim3 g2(TT, NPAIR);
    softmax_kl_kernel<<<g2, 256>>>(lens, targets);

    ctc_kernel<<<NB, 256>>>(lens, targets, tlens);

    reduce_kernel<<<1, 256>>>(out);
}

// round 13
// speedup vs baseline: 3.1582x; 1.0705x over previous
#include <cuda_runtime.h>
#include <cuda_fp16.h>
#include <math.h>
#include <stdint.h>

#define TT   1000
#define NB   32
#define NPAIR 16
#define VV   2000
#define CC   512
#define UU   100
#define SS   201
#define EXT  104
#define NEGF (-1.0e30f)

#define BMg 128
#define BNg 128
#define BKg 32
#define NSTG (CC / BKg)
#define ROWB 80
#define PLANE_B (BMg * ROWB)      // 10240
#define STAGE_B (2 * PLANE_B)     // Ah, Wh
#define GEMM_SMEM (2 * STAGE_B)   // 40960

__device__ __half g_logits[(size_t)NB * TT * VV];   // fp16 logits (128 MB)
__device__ float g_lp[(size_t)NB * TT * EXT];       // natural-log probs at ext classes
__device__ float g_kl[NPAIR * TT];
__device__ float g_ctc[NB];
__device__ int   g_ckflag[NPAIR * 64];              // per (pair, chunk) completion counters
__device__ __half g_Ah[(size_t)NB * TT * CC];
__device__ __half g_Wh[(size_t)2048 * CC];          // vocab padded to 2048 rows

__device__ __forceinline__ uint32_t s2u(const void* p) {
    uint32_t a;
    asm("{ .reg .u64 t; cvta.to.shared.u64 t, %1; cvt.u32.u64 %0, t; }" : "=r"(a) : "l"(p));
    return a;
}
__device__ __forceinline__ void cp_async16(uint32_t dst, const void* src) {
    asm volatile("cp.async.cg.shared.global [%0], [%1], 16;" :: "r"(dst), "l"(src) : "memory");
}
__device__ __forceinline__ void cp_commit() {
    asm volatile("cp.async.commit_group;" ::: "memory");
}
template <int N>
__device__ __forceinline__ void cp_wait() {
    asm volatile("cp.async.wait_group %0;" :: "n"(N) : "memory");
}
__device__ __forceinline__ void ldsm4(uint32_t& r0, uint32_t& r1, uint32_t& r2, uint32_t& r3,
                                      uint32_t a) {
    asm volatile("ldmatrix.sync.aligned.m8n8.x4.shared.b16 {%0,%1,%2,%3}, [%4];"
                 : "=r"(r0), "=r"(r1), "=r"(r2), "=r"(r3) : "r"(a));
}
__device__ __forceinline__ void mma16816h(float* c, const uint32_t* a, const uint32_t* b) {
    asm volatile(
        "mma.sync.aligned.m16n8k16.row.col.f32.f16.f16.f32 "
        "{%0,%1,%2,%3}, {%4,%5,%6,%7}, {%8,%9}, {%0,%1,%2,%3};"
        : "+f"(c[0]), "+f"(c[1]), "+f"(c[2]), "+f"(c[3])
        : "r"(a[0]), "r"(a[1]), "r"(a[2]), "r"(a[3]), "r"(b[0]), "r"(b[1]));
}

// ---- block reductions ----
__device__ __forceinline__ float bsum(float v, float* sh) {
    #pragma unroll
    for (int o = 16; o; o >>= 1) v += __shfl_xor_sync(0xffffffffu, v, o);
    __syncthreads();
    if ((threadIdx.x & 31) == 0) sh[threadIdx.x >> 5] = v;
    __syncthreads();
    if (threadIdx.x == 0) {
        float t = 0.f;
        #pragma unroll
        for (int i = 0; i < 8; i++) t += sh[i];
        sh[0] = t;
    }
    __syncthreads();
    return sh[0];
}
__device__ __forceinline__ void bmax2(float& x, float& y, float* sh) {
    #pragma unroll
    for (int o = 16; o; o >>= 1) {
        x = fmaxf(x, __shfl_xor_sync(0xffffffffu, x, o));
        y = fmaxf(y, __shfl_xor_sync(0xffffffffu, y, o));
    }
    __syncthreads();
    if ((threadIdx.x & 31) == 0) {
        sh[(threadIdx.x >> 5) * 2]     = x;
        sh[(threadIdx.x >> 5) * 2 + 1] = y;
    }
    __syncthreads();
    if (threadIdx.x == 0) {
        float tx = sh[0], ty = sh[1];
        #pragma unroll
        for (int i = 1; i < 8; i++) {
            tx = fmaxf(tx, sh[i * 2]);
            ty = fmaxf(ty, sh[i * 2 + 1]);
        }
        sh[0] = tx; sh[1] = ty;
    }
    __syncthreads();
    x = sh[0]; y = sh[1];
}
__device__ __forceinline__ void bsum2(float& x, float& y, float* sh) {
    #pragma unroll
    for (int o = 16; o; o >>= 1) {
        x += __shfl_xor_sync(0xffffffffu, x, o);
        y += __shfl_xor_sync(0xffffffffu, y, o);
    }
    __syncthreads();
    if ((threadIdx.x & 31) == 0) {
        sh[(threadIdx.x >> 5) * 2]     = x;
        sh[(threadIdx.x >> 5) * 2 + 1] = y;
    }
    __syncthreads();
    if (threadIdx.x == 0) {
        float tx = 0.f, ty = 0.f;
        #pragma unroll
        for (int i = 0; i < 8; i++) {
            tx += sh[i * 2];
            ty += sh[i * 2 + 1];
        }
        sh[0] = tx; sh[1] = ty;
    }
    __syncthreads();
    x = sh[0]; y = sh[1];
}

// ======================= 0) fp32 -> fp16 round (A and W) + flag reset =======================
__global__ __launch_bounds__(256)
void convert_kernel(const float* __restrict__ enc, const float* __restrict__ W) {
    const int NA4 = NB * TT * CC / 4;
    const int NW4 = 2048 * CC / 4;
    int i = blockIdx.x * 256 + threadIdx.x;
    if (i < NPAIR * 64) g_ckflag[i] = 0;          // reset producer/consumer flags each launch
    if (i < NA4) {
        float4 v = ((const float4*)enc)[i];
        float a[4] = {v.x, v.y, v.z, v.w};
        union { __half h[4]; uint2 u; } H;
        #pragma unroll
        for (int k = 0; k < 4; k++) H.h[k] = __float2half_rn(a[k]);
        *(uint2*)(g_Ah + (size_t)i * 4) = H.u;
    } else if (i < NA4 + NW4) {
        int j = i - NA4;
        int row = j >> 7;
        float4 v = (row < VV) ? ((const float4*)W)[j] : make_float4(0.f, 0.f, 0.f, 0.f);
        float a[4] = {v.x, v.y, v.z, v.w};
        union { __half h[4]; uint2 u; } H;
        #pragma unroll
        for (int k = 0; k < 4; k++) H.h[k] = __float2half_rn(a[k]);
        *(uint2*)(g_Wh + (size_t)j * 4) = H.u;
    }
}

// ======================= 1) HMMA GEMM (single fp16 product, fp16 logits out) =======================
__device__ __forceinline__ void issue_stage(int rm0, int v0, int k0, uint32_t stb) {
    const int tid = threadIdx.x;
    #pragma unroll
    for (int j = 0; j < 4; j++) {
        const int g = tid + j * 256;
        const int plane = g >> 9;
        const int idx = g & 511;
        const int row = idx >> 2;
        const int cch = idx & 3;
        const __half* sp;
        int grow;
        if (plane == 0) { sp = g_Ah; grow = rm0 + row; }
        else            { sp = g_Wh; grow = v0 + row; }
        uint32_t dst = stb + plane * PLANE_B + row * ROWB + cch * 16;
        cp_async16(dst, sp + (size_t)grow * CC + k0 + cch * 8);
    }
    cp_commit();
}

__global__ __launch_bounds__(256, 2)
void gemm_hmma_kernel(const int* __restrict__ lens, const float* __restrict__ bias) {
    const int v0  = blockIdx.x * BNg;
    const int rm0 = blockIdx.y * BMg;
    {
        int b_first = rm0 / TT, b_last = (rm0 + BMg - 1) / TT;
        bool act = false;
        for (int b = b_first; b <= b_last && b < NB; b++) {
            int t_lo = max(rm0, b * TT) - b * TT;
            if (t_lo < lens[b]) act = true;
        }
        if (!act) return;
    }
    extern __shared__ char smem[];
    const uint32_t sb = s2u(smem);
    const int tid = threadIdx.x;
    const int lane = tid & 31;
    const int wid = tid >> 5;
    const int wm = wid >> 2;
    const int wn = wid & 3;

    const uint32_t abase = (uint32_t)((wm * 64 + (lane & 15)) * ROWB + (lane >> 4) * 16);
    const int n_l = (lane & 7) + ((lane >> 4) << 3);
    const uint32_t bbase = (uint32_t)((wn * 32 + n_l) * ROWB + ((lane >> 3) & 1) * 16);

    float acc[4][4][4];
    #pragma unroll
    for (int i = 0; i < 4; i++)
        #pragma unroll
        for (int j = 0; j < 4; j++)
            #pragma unroll
            for (int q = 0; q < 4; q++) acc[i][j][q] = 0.f;

    issue_stage(rm0, v0, 0, sb);

    for (int kt = 0; kt < NSTG; kt++) {
        const uint32_t stb = sb + (kt & 1) * STAGE_B;
        if (kt + 1 < NSTG) {
            issue_stage(rm0, v0, (kt + 1) * BKg, sb + ((kt + 1) & 1) * STAGE_B);
            cp_wait<1>();
        } else {
            cp_wait<0>();
        }
        __syncthreads();

        #pragma unroll
        for (int ks = 0; ks < 2; ks++) {
            uint32_t bh[4][2];
            #pragma unroll
            for (int pr = 0; pr < 2; pr++) {
                uint32_t addr = stb + PLANE_B + bbase + pr * (16 * ROWB) + ks * 32;
                ldsm4(bh[pr * 2][0], bh[pr * 2][1], bh[pr * 2 + 1][0], bh[pr * 2 + 1][1], addr);
            }
            #pragma unroll
            for (int mt = 0; mt < 4; mt++) {
                uint32_t ah[4];
                uint32_t addr = stb + abase + mt * (16 * ROWB) + ks * 32;
                ldsm4(ah[0], ah[1], ah[2], ah[3], addr);
                #pragma unroll
                for (int nt = 0; nt < 4; nt++) {
                    mma16816h(acc[mt][nt], ah, bh[nt]);
                }
            }
        }
        __syncthreads();
    }

    const int r0 = rm0 + wm * 64 + (lane >> 2);
    const int c0 = v0 + wn * 32 + (lane & 3) * 2;
    #pragma unroll
    for (int nt = 0; nt < 4; nt++) {
        const int col = c0 + nt * 8;
        if (col < VV) {
            const float b0 = bias[col], b1 = bias[col + 1];
            #pragma unroll
            for (int mt = 0; mt < 4; mt++) {
                const int row = r0 + mt * 16;
                __half* d = g_logits + (size_t)row * VV + col;
                *(__half2*)d = __floats2half2_rn(acc[mt][nt][0] + b0, acc[mt][nt][1] + b1);
                *(__half2*)(d + 8 * VV) = __floats2half2_rn(acc[mt][nt][2] + b0, acc[mt][nt][3] + b1);
            }
        }
    }
}

// ======================= 2) fused softmax+KL (producer) + CTC (consumer) =======================
// grid = 32 + TT*NPAIR. Blocks 0..31: CTC (one per sequence). Blocks 32+: softmax for
// (p, t) with t ascending in blockIdx so early chunks complete first. Softmax blocks
// publish per-(pair, 16-step-chunk) counters; CTC blocks wait on them before prefetch.
__global__ __launch_bounds__(256)
void softmax_ctc_kernel(const int* __restrict__ lens, const int* __restrict__ targets,
                        const int* __restrict__ tlens) {
    __shared__ float sh[16];
    __shared__ float al[2][SS + 3];
    __shared__ float lpb[2][16][EXT];
    const int bid = blockIdx.x;
    const int tid = threadIdx.x;

    if (bid >= 32) {
        // ---------------- softmax role ----------------
        const int li = bid - 32;
        const int p = li & 15;
        const int t = li >> 4;
        const int pb = p * TT + t;

        if (t < lens[p]) {
            const size_t r1 = (size_t)p * TT + t;
            const size_t r2 = (size_t)(p + NPAIR) * TT + t;
            const __half* L1 = g_logits + r1 * VV;
            const __half* L2 = g_logits + r2 * VV;
            const uint4* L1v = (const uint4*)L1;
            const uint4* L2v = (const uint4*)L2;

            float v1[8], v2[8];
            float m1 = -3.4e38f, m2 = -3.4e38f;
            const bool act = (tid < 250);
            if (act) {
                union { uint4 u; __half2 h[4]; } U1, U2;
                U1.u = L1v[tid];
                U2.u = L2v[tid];
                #pragma unroll
                for (int k = 0; k < 4; k++) {
                    float2 f1 = __half22float2(U1.h[k]);
                    float2 f2 = __half22float2(U2.h[k]);
                    v1[k * 2] = f1.x; v1[k * 2 + 1] = f1.y;
                    v2[k * 2] = f2.x; v2[k * 2 + 1] = f2.y;
                }
                #pragma unroll
                for (int k = 0; k < 8; k++) {
                    m1 = fmaxf(m1, v1[k]);
                    m2 = fmaxf(m2, v2[k]);
                }
            }
            bmax2(m1, m2, sh);

            float e1[8], e2[8];
            float s1 = 0.f, s2 = 0.f;
            if (act) {
                #pragma unroll
                for (int k = 0; k < 8; k++) {
                    e1[k] = __expf(v1[k] - m1); s1 += e1[k];
                    e2[k] = __expf(v2[k] - m2); s2 += e2[k];
                }
            }
            bsum2(s1, s2, sh);
            const float lZ1 = __logf(s1), lZ2 = __logf(s2);
            const float iZ1 = 1.f / s1,   iZ2 = 1.f / s2;

            float kl = 0.f;
            if (act) {
                #pragma unroll
                for (int k = 0; k < 8; k++) {
                    float p1 = v1[k] - m1 - lZ1;
                    float p2 = v2[k] - m2 - lZ2;
                    kl += (p1 - p2) * (e1[k] * iZ1 - e2[k] * iZ2);
                }
            }
            kl = bsum(kl, sh);
            if (tid == 0) g_kl[pb] = kl;

            if (tid < 1 + UU) {
                int c = (tid == 0) ? 0 : targets[p * UU + (tid - 1)];
                g_lp[r1 * EXT + tid] = __half2float(L1[c]) - m1 - lZ1;
                g_lp[r2 * EXT + tid] = __half2float(L2[c]) - m2 - lZ2;
            }
        } else {
            if (tid == 0) g_kl[pb] = 0.f;
        }
        // publish completion (t>=len blocks count too; consumer expects min(16, TT-16c))
        __threadfence();
        __syncthreads();
        if (tid == 0) atomicAdd(&g_ckflag[p * 64 + (t >> 4)], 1);
        return;
    }

    // ---------------- CTC role (R4 recursion + chunk waits) ----------------
    const int b = bid;
    const int p = b & 15;
    const int len = lens[b];
    const int* tg = targets + b * UU;

    const int s = tid;
    const bool isstate = (s < SS);
    const int u = (s - 1) >> 1;
    const int pidx = (s & 1) ? (1 + u) : 0;
    bool can_skip = false;
    if (isstate && (s & 1) && s >= 3) can_skip = (tg[u] != tg[u - 1]);

    const float* base = g_lp + (size_t)b * TT * EXT;
    const int nchunk = (len + 15) / 16;

    // wait for chunk 0
    if (tid == 0) {
        volatile int* f = (volatile int*)&g_ckflag[p * 64];
        while (*f < 16) __nanosleep(64);
    }
    __syncthreads();

    {
        int n0 = min(16, len) * EXT;
        for (int i = tid; i < n0; i += 256) (&lpb[0][0][0])[i] = base[i];
    }
    __syncthreads();

    if (isstate) {
        float v = NEGF;
        if (s == 0) v = lpb[0][0][0];
        if (s == 1) v = lpb[0][0][1];
        al[0][s] = v;
    }
    __syncthreads();

    int curbuf = 0;
    float stage[7];
    for (int c = 0; c < nchunk; c++) {
        int nn = 0;
        const int tn0 = (c + 1) * 16;
        if (c + 1 < nchunk) {
            // wait for chunk c+1 to be produced
            if (tid == 0) {
                const int expected = min(16, TT - tn0);
                volatile int* f = (volatile int*)&g_ckflag[p * 64 + c + 1];
                while (*f < expected) __nanosleep(64);
            }
            __syncthreads();
            nn = (min(tn0 + 16, len) - tn0) * EXT;
            #pragma unroll
            for (int q = 0; q < 7; q++) {
                int i = tid + q * 256;
                stage[q] = (i < nn) ? base[(size_t)tn0 * EXT + i] : 0.f;
            }
        }
        const int t0 = c * 16;
        const int te = min(t0 + 16, len);
        for (int t = max(t0, 1); t < te; t++) {
            if (isstate) {
                const float lp = lpb[c & 1][t - t0][pidx];
                const float a  = al[curbuf][s];
                const float bb = (s >= 1) ? al[curbuf][s - 1] : NEGF;
                const float cc = can_skip ? al[curbuf][s - 2] : NEGF;
                const float m = fmaxf(a, fmaxf(bb, cc));
                const float r = __expf(a - m) + __expf(bb - m) + __expf(cc - m);
                al[curbuf ^ 1][s] = m + __logf(r) + lp;
            }
            __syncthreads();
            curbuf ^= 1;
        }
        if (c + 1 < nchunk) {
            #pragma unroll
            for (int q = 0; q < 7; q++) {
                int i = tid + q * 256;
                if (i < nn) (&lpb[(c + 1) & 1][0][0])[i] = stage[q];
            }
        }
        __syncthreads();
    }

    if (tid == 0) {
        const int e = 2 * tlens[b];
        const float a = al[curbuf][e];
        const float bb = al[curbuf][e - 1];
        const float m = fmaxf(a, bb);
        g_ctc[b] = -(m + __logf(__expf(a - m) + __expf(bb - m)));
    }
}

// ======================= 3) final reduction =======================
__global__ __launch_bounds__(256)
void reduce_kernel(float* __restrict__ out) {
    __shared__ float sh[8];
    const int tid = threadIdx.x;
    float skl = 0.f;
    for (int i = tid; i < NPAIR * TT; i += 256) skl += g_kl[i];
    float sctc = (tid < NB) ? g_ctc[tid] : 0.f;
    skl = bsum(skl, sh);
    sctc = bsum(sctc, sh);
    if (tid == 0) {
        out[0] = 0.5f * sctc;
        out[1] = 0.5f * skl;
    }
}

extern "C" void kernel_launch(void* const* d_in, const int* in_sizes, int n_in,
                              void* d_out, int out_size) {
    const float* enc     = (const float*)d_in[0];
    const float* W       = (const float*)d_in[1];
    const float* bias    = (const float*)d_in[2];
    const int*   lens    = (const int*)d_in[3];
    const int*   targets = (const int*)d_in[4];
    const int*   tlens   = (const int*)d_in[5];
    float* out = (float*)d_out;

    cudaFuncSetAttribute(gemm_hmma_kernel, cudaFuncAttributeMaxDynamicSharedMemorySize, GEMM_SMEM);

    const int NA4 = NB * TT * CC / 4;
    const int NW4 = 2048 * CC / 4;
    convert_kernel<<<(NA4 + NW4 + 255) / 256, 256>>>(enc, W);

    dim3 gg((VV + BNg - 1) / BNg, (NB * TT) / BMg);
    gemm_hmma_kernel<<<gg, 256, GEMM_SMEM>>>(lens, bias);

    softmax_ctc_kernel<<<32 + TT * NPAIR, 256>>>(lens, targets, tlens);

    reduce_kernel<<<1, 256>>>(out);
}